// round 5
// baseline (speedup 1.0000x reference)
#include <cuda_runtime.h>
#include <math.h>

// Problem constants (fixed shapes)
#define T_TOK 4096
#define DIM   512
#define FDIM  1024
#define NE    8
#define TOPK  2
#define NPAIR (T_TOK*TOPK)

// ---------------- device scratch (static; no runtime allocation) ----------------
__device__ int   g_cnt[NE];
__device__ int   g_list[NE*T_TOK];   // packed (token<<1)|k
__device__ float g_wgt [NE*T_TOK];   // normalized top-k weight for that pair
__device__ float g_sumP[NE];
__device__ float g_zsum;
__device__ float g_hidden[(size_t)NPAIR*FDIM];  // silu(g)*u per pair  (33.5 MB)
__device__ float g_pout [(size_t)NPAIR*DIM];    // per-pair down-proj   (16.8 MB)

// ---------------- f32x2 packed-FMA helpers (sm_100+ PTX) ----------------
__device__ __forceinline__ unsigned long long pack2(float lo, float hi) {
    unsigned long long r;
    asm("mov.b64 %0, {%1, %2};" : "=l"(r) : "f"(lo), "f"(hi));
    return r;
}
__device__ __forceinline__ float2 unpack2(unsigned long long v) {
    float2 r;
    asm("mov.b64 {%0, %1}, %2;" : "=f"(r.x), "=f"(r.y) : "l"(v));
    return r;
}
__device__ __forceinline__ void ffma2(unsigned long long& acc,
                                      unsigned long long a, unsigned long long b) {
    asm("fma.rn.f32x2 %0, %1, %2, %0;" : "+l"(acc) : "l"(a), "l"(b));
}

// ---------------- zero per-launch accumulators ----------------
__global__ void zero_kernel() {
    int i = threadIdx.x;
    if (i < NE) { g_cnt[i] = 0; g_sumP[i] = 0.f; }
    if (i == 0) g_zsum = 0.f;
}

// ---------------- router: logits, softmax, top-2, lists, aux sums ----------------
__global__ void router_kernel(const float* __restrict__ x, const float* __restrict__ rw) {
    int gw   = (blockIdx.x * blockDim.x + threadIdx.x) >> 5;   // token
    int lane = threadIdx.x & 31;
    if (gw >= T_TOK) return;

    const float4* xp = (const float4*)(x + (size_t)gw * DIM);
    float4 xv[4];
#pragma unroll
    for (int i = 0; i < 4; i++) xv[i] = xp[lane * 4 + i];

    float logit[NE];
#pragma unroll
    for (int e = 0; e < NE; e++) {
        const float4* wp = (const float4*)(rw + (size_t)e * DIM);
        float acc = 0.f;
#pragma unroll
        for (int i = 0; i < 4; i++) {
            float4 w4 = wp[lane * 4 + i];
            acc += xv[i].x * w4.x + xv[i].y * w4.y + xv[i].z * w4.z + xv[i].w * w4.w;
        }
#pragma unroll
        for (int o = 16; o > 0; o >>= 1) acc += __shfl_xor_sync(0xffffffffu, acc, o);
        logit[e] = acc;
    }

    if (lane == 0) {
        float m = logit[0];
#pragma unroll
        for (int e = 1; e < NE; e++) m = fmaxf(m, logit[e]);
        float p[NE]; float se = 0.f;
#pragma unroll
        for (int e = 0; e < NE; e++) { p[e] = expf(logit[e] - m); se += p[e]; }
        float inv = 1.f / se;

        int i0 = 0; float v0 = -1.f;
#pragma unroll
        for (int e = 0; e < NE; e++) if (p[e] > v0) { v0 = p[e]; i0 = e; }
        int i1 = -1; float v1 = -1.f;
#pragma unroll
        for (int e = 0; e < NE; e++) if (e != i0 && p[e] > v1) { v1 = p[e]; i1 = e; }

        float s2 = v0 + v1;
        float w0 = v0 / s2, w1 = v1 / s2;

        int pos0 = atomicAdd(&g_cnt[i0], 1);
        g_list[i0 * T_TOK + pos0] = (gw << 1);
        g_wgt [i0 * T_TOK + pos0] = w0;
        int pos1 = atomicAdd(&g_cnt[i1], 1);
        g_list[i1 * T_TOK + pos1] = (gw << 1) | 1;
        g_wgt [i1 * T_TOK + pos1] = w1;

#pragma unroll
        for (int e = 0; e < NE; e++) atomicAdd(&g_sumP[e], p[e] * inv);
        float lse = m + logf(se);
        atomicAdd(&g_zsum, lse * lse);
    }
}

// ---------------- phase A: hidden = silu(Xe@gate) * (Xe@up), gathered rows ----------------
#define BMA 128
#define BNA 64
#define BKA 16
__global__ void __launch_bounds__(256) gateup_kernel(const float* __restrict__ x,
                                                     const float* __restrict__ gw,
                                                     const float* __restrict__ uw) {
    int e = blockIdx.z;
    int cnt = g_cnt[e];
    int row0 = blockIdx.y * BMA;
    if (row0 >= cnt) return;
    int col0 = blockIdx.x * BNA;

    __shared__ __align__(16) float sA [BKA][BMA];
    __shared__ __align__(16) float sBg[BKA][BNA];
    __shared__ __align__(16) float sBu[BKA][BNA];
    __shared__ int sTok[BMA];

    int tid = threadIdx.x;
    for (int i = tid; i < BMA; i += 256) {
        int r = row0 + i;
        sTok[i] = (r < cnt) ? g_list[e * T_TOK + r] : -1;
    }
    __syncthreads();

    int tx = tid & 15, ty = tid >> 4;
    unsigned long long accg[8][2], accu[8][2];
#pragma unroll
    for (int i = 0; i < 8; i++) {
        accg[i][0] = accg[i][1] = 0ull;
        accu[i][0] = accu[i][1] = 0ull;
    }

    const float* gbase = gw + (size_t)e * DIM * FDIM + col0;
    const float* ubase = uw + (size_t)e * DIM * FDIM + col0;

    int ra = tid >> 1;           // 0..127  A row
    int ca = (tid & 1) * 8;      // 0 / 8   A col block
    int entryA = sTok[ra];
    const float* xrow = (entryA >= 0) ? (x + (size_t)(entryA >> 1) * DIM) : x;
    int kb  = tid >> 4;          // 0..15   B row
    int cb  = (tid & 15) * 4;    // B col

    for (int kt = 0; kt < DIM; kt += BKA) {
        float4 a0, a1;
        if (entryA >= 0) {
            a0 = *(const float4*)(xrow + kt + ca);
            a1 = *(const float4*)(xrow + kt + ca + 4);
        } else {
            a0 = make_float4(0.f,0.f,0.f,0.f); a1 = a0;
        }
        float4 bg4 = *(const float4*)(gbase + (size_t)(kt + kb) * FDIM + cb);
        float4 bu4 = *(const float4*)(ubase + (size_t)(kt + kb) * FDIM + cb);
        __syncthreads();
        sA[ca+0][ra] = a0.x; sA[ca+1][ra] = a0.y; sA[ca+2][ra] = a0.z; sA[ca+3][ra] = a0.w;
        sA[ca+4][ra] = a1.x; sA[ca+5][ra] = a1.y; sA[ca+6][ra] = a1.z; sA[ca+7][ra] = a1.w;
        *(float4*)&sBg[kb][cb] = bg4;
        *(float4*)&sBu[kb][cb] = bu4;
        __syncthreads();

#pragma unroll
        for (int kk = 0; kk < BKA; kk++) {
            float4 av0 = *(const float4*)&sA[kk][ty * 8];
            float4 av1 = *(const float4*)&sA[kk][ty * 8 + 4];
            float4 bg  = *(const float4*)&sBg[kk][tx * 4];
            float4 bu  = *(const float4*)&sBu[kk][tx * 4];
            unsigned long long bg01 = pack2(bg.x, bg.y), bg23 = pack2(bg.z, bg.w);
            unsigned long long bu01 = pack2(bu.x, bu.y), bu23 = pack2(bu.z, bu.w);
            float a[8] = {av0.x, av0.y, av0.z, av0.w, av1.x, av1.y, av1.z, av1.w};
#pragma unroll
            for (int i = 0; i < 8; i++) {
                unsigned long long aa = pack2(a[i], a[i]);
                ffma2(accg[i][0], aa, bg01);
                ffma2(accg[i][1], aa, bg23);
                ffma2(accu[i][0], aa, bu01);
                ffma2(accu[i][1], aa, bu23);
            }
        }
    }

#pragma unroll
    for (int i = 0; i < 8; i++) {
        int r = ty * 8 + i;
        int entry = sTok[r];
        if (entry < 0) continue;
        float2 g0 = unpack2(accg[i][0]), g1 = unpack2(accg[i][1]);
        float2 u0 = unpack2(accu[i][0]), u1 = unpack2(accu[i][1]);
        float4 h;
        h.x = u0.x * (g0.x / (1.f + expf(-g0.x)));
        h.y = u0.y * (g0.y / (1.f + expf(-g0.y)));
        h.z = u1.x * (g1.x / (1.f + expf(-g1.x)));
        h.w = u1.y * (g1.y / (1.f + expf(-g1.y)));
        *(float4*)(g_hidden + (size_t)entry * FDIM + col0 + tx * 4) = h;
    }
}

// ---------------- phase B: pair_out = w * (hidden @ down) ----------------
#define BMB 128
#define BNB 128
#define BKB 16
__global__ void __launch_bounds__(256) down_kernel(const float* __restrict__ dw) {
    int e = blockIdx.z;
    int cnt = g_cnt[e];
    int row0 = blockIdx.y * BMB;
    if (row0 >= cnt) return;
    int col0 = blockIdx.x * BNB;

    __shared__ __align__(16) float sA[BKB][BMB];
    __shared__ __align__(16) float sB[BKB][BNB];
    __shared__ int   sTok[BMB];
    __shared__ float sW  [BMB];

    int tid = threadIdx.x;
    for (int i = tid; i < BMB; i += 256) {
        int r = row0 + i;
        sTok[i] = (r < cnt) ? g_list[e * T_TOK + r] : -1;
        sW[i]   = (r < cnt) ? g_wgt [e * T_TOK + r] : 0.f;
    }
    __syncthreads();

    int tx = tid & 15, ty = tid >> 4;
    unsigned long long acc[8][4];
#pragma unroll
    for (int i = 0; i < 8; i++)
#pragma unroll
        for (int j = 0; j < 4; j++) acc[i][j] = 0ull;

    int ra = tid >> 1;         // A row
    int ca = (tid & 1) * 8;
    int entryA = sTok[ra];
    const float* hrow = (entryA >= 0) ? (g_hidden + (size_t)entryA * FDIM) : g_hidden;
    int kb  = tid >> 4;        // 0..15 B row
    int cbB = (tid & 15) * 8;  // B col
    const float* dbase = dw + (size_t)e * FDIM * DIM + col0;

    for (int kt = 0; kt < FDIM; kt += BKB) {
        float4 a0, a1;
        if (entryA >= 0) {
            a0 = *(const float4*)(hrow + kt + ca);
            a1 = *(const float4*)(hrow + kt + ca + 4);
        } else {
            a0 = make_float4(0.f,0.f,0.f,0.f); a1 = a0;
        }
        float4 b0 = *(const float4*)(dbase + (size_t)(kt + kb) * DIM + cbB);
        float4 b1 = *(const float4*)(dbase + (size_t)(kt + kb) * DIM + cbB + 4);
        __syncthreads();
        sA[ca+0][ra] = a0.x; sA[ca+1][ra] = a0.y; sA[ca+2][ra] = a0.z; sA[ca+3][ra] = a0.w;
        sA[ca+4][ra] = a1.x; sA[ca+5][ra] = a1.y; sA[ca+6][ra] = a1.z; sA[ca+7][ra] = a1.w;
        *(float4*)&sB[kb][cbB]     = b0;
        *(float4*)&sB[kb][cbB + 4] = b1;
        __syncthreads();

#pragma unroll
        for (int kk = 0; kk < BKB; kk++) {
            float4 av0 = *(const float4*)&sA[kk][ty * 8];
            float4 av1 = *(const float4*)&sA[kk][ty * 8 + 4];
            float4 bv0 = *(const float4*)&sB[kk][tx * 8];
            float4 bv1 = *(const float4*)&sB[kk][tx * 8 + 4];
            unsigned long long b01 = pack2(bv0.x, bv0.y), b23 = pack2(bv0.z, bv0.w);
            unsigned long long b45 = pack2(bv1.x, bv1.y), b67 = pack2(bv1.z, bv1.w);
            float a[8] = {av0.x, av0.y, av0.z, av0.w, av1.x, av1.y, av1.z, av1.w};
#pragma unroll
            for (int i = 0; i < 8; i++) {
                unsigned long long aa = pack2(a[i], a[i]);
                ffma2(acc[i][0], aa, b01);
                ffma2(acc[i][1], aa, b23);
                ffma2(acc[i][2], aa, b45);
                ffma2(acc[i][3], aa, b67);
            }
        }
    }

#pragma unroll
    for (int i = 0; i < 8; i++) {
        int r = ty * 8 + i;
        int entry = sTok[r];
        if (entry < 0) continue;
        float w = sW[r];
        float2 y0 = unpack2(acc[i][0]), y1 = unpack2(acc[i][1]);
        float2 y2 = unpack2(acc[i][2]), y3 = unpack2(acc[i][3]);
        float4 o0 = make_float4(w*y0.x, w*y0.y, w*y1.x, w*y1.y);
        float4 o1 = make_float4(w*y2.x, w*y2.y, w*y3.x, w*y3.y);
        float* op = g_pout + (size_t)entry * DIM + col0 + tx * 8;
        *(float4*)(op)     = o0;
        *(float4*)(op + 4) = o1;
    }
}

// ---------------- combine the two pair slots per token ----------------
__global__ void combine_kernel(float* __restrict__ out) {
    int i = blockIdx.x * blockDim.x + threadIdx.x;        // float4 index
    const int N4  = T_TOK * DIM / 4;
    const int D4  = DIM / 4;
    if (i >= N4) return;
    int t = i / D4, c = i % D4;
    const float4* p = (const float4*)g_pout;
    float4 a = p[(size_t)(2 * t) * D4 + c];
    float4 b = p[(size_t)(2 * t + 1) * D4 + c];
    ((float4*)out)[i] = make_float4(a.x + b.x, a.y + b.y, a.z + b.z, a.w + b.w);
}

// ---------------- aux loss ----------------
__global__ void finalize_kernel(float* __restrict__ out, int out_size) {
    float lb = 0.f;
#pragma unroll
    for (int e = 0; e < NE; e++)
        lb += ((float)g_cnt[e] / (float)NPAIR) * (g_sumP[e] / (float)T_TOK);
    float aux = 0.01f * (float)NE * lb + 0.001f * (g_zsum / (float)T_TOK);
    out[out_size - 1] = aux;
}

// ---------------- launch ----------------
extern "C" void kernel_launch(void* const* d_in, const int* in_sizes, int n_in,
                              void* d_out, int out_size) {
    const float* x  = (const float*)d_in[0];
    const float* rw = (const float*)d_in[1];
    const float* gw = (const float*)d_in[2];
    const float* uw = (const float*)d_in[3];
    const float* dw = (const float*)d_in[4];
    float* out = (float*)d_out;

    zero_kernel<<<1, 32>>>();
    router_kernel<<<T_TOK / 4, 128>>>(x, rw);
    gateup_kernel<<<dim3(FDIM / BNA, T_TOK / BMA, NE), 256>>>(x, gw, uw);
    down_kernel<<<dim3(DIM / BNB, T_TOK / BMB, NE), 256>>>(dw);
    combine_kernel<<<(T_TOK * DIM / 4 + 255) / 256, 256>>>(out);
    finalize_kernel<<<1, 1>>>(out, out_size);
}

// round 7
// speedup vs baseline: 1.6760x; 1.6760x over previous
#include <cuda_runtime.h>
#include <cuda_bf16.h>
#include <math.h>
#include <stdint.h>

// Problem constants (fixed shapes)
#define T_TOK 4096
#define DIM   512
#define FDIM  1024
#define NE    8
#define TOPK  2
#define NPAIR (T_TOK*TOPK)

// ---------------- device scratch (static; no runtime allocation) ----------------
__device__ int   g_cnt[NE];
__device__ int   g_list[NE*T_TOK];   // packed (token<<1)|k
__device__ float g_wgt [NE*T_TOK];   // normalized top-k weight for that pair
__device__ float g_sumP[NE];
__device__ float g_zsum;

// bf16 hi/lo splits
__device__ __nv_bfloat16 g_xh[(size_t)T_TOK*DIM];
__device__ __nv_bfloat16 g_xl[(size_t)T_TOK*DIM];
__device__ __nv_bfloat16 g_gTh[(size_t)NE*FDIM*DIM];  // gate^T [E][F][D] K-major
__device__ __nv_bfloat16 g_gTl[(size_t)NE*FDIM*DIM];
__device__ __nv_bfloat16 g_uTh[(size_t)NE*FDIM*DIM];  // up^T
__device__ __nv_bfloat16 g_uTl[(size_t)NE*FDIM*DIM];
__device__ __nv_bfloat16 g_dTh[(size_t)NE*DIM*FDIM];  // down^T [E][D][F] K-major
__device__ __nv_bfloat16 g_dTl[(size_t)NE*DIM*FDIM];
__device__ __nv_bfloat16 g_hh[(size_t)NPAIR*FDIM];    // hidden hi
__device__ __nv_bfloat16 g_hl[(size_t)NPAIR*FDIM];    // hidden lo
__device__ float g_pout[(size_t)NPAIR*DIM];           // per-pair down-proj

// ================= PTX helpers (family-portable: sm_80+ / sm_103 baseline) =================
__device__ __forceinline__ uint32_t smem_u32(const void* p) {
    uint32_t a;
    asm("{ .reg .u64 t; cvta.to.shared.u64 t, %1; cvt.u32.u64 %0, t; }" : "=r"(a) : "l"(p));
    return a;
}
__device__ __forceinline__ void cp16(uint32_t dst, const void* src, uint32_t bytes) {
    asm volatile("cp.async.cg.shared.global [%0], [%1], 16, %2;"
                 :: "r"(dst), "l"(src), "r"(bytes) : "memory");
}
#define CP_COMMIT() asm volatile("cp.async.commit_group;" ::: "memory")
#define CP_WAIT1()  asm volatile("cp.async.wait_group 1;" ::: "memory")
#define CP_WAIT0()  asm volatile("cp.async.wait_group 0;" ::: "memory")

__device__ __forceinline__ void ldsm_x4(uint32_t* r, uint32_t addr) {
    asm volatile("ldmatrix.sync.aligned.m8n8.x4.shared.b16 {%0,%1,%2,%3}, [%4];"
        : "=r"(r[0]), "=r"(r[1]), "=r"(r[2]), "=r"(r[3]) : "r"(addr));
}
__device__ __forceinline__ void ldsm_x2(uint32_t* r, uint32_t addr) {
    asm volatile("ldmatrix.sync.aligned.m8n8.x2.shared.b16 {%0,%1}, [%2];"
        : "=r"(r[0]), "=r"(r[1]) : "r"(addr));
}
__device__ __forceinline__ void mma_bf16(float* d, const uint32_t* a, const uint32_t* b) {
    asm volatile("mma.sync.aligned.m16n8k16.row.col.f32.bf16.bf16.f32 "
        "{%0,%1,%2,%3}, {%4,%5,%6,%7}, {%8,%9}, {%0,%1,%2,%3};"
        : "+f"(d[0]), "+f"(d[1]), "+f"(d[2]), "+f"(d[3])
        : "r"(a[0]), "r"(a[1]), "r"(a[2]), "r"(a[3]), "r"(b[0]), "r"(b[1]));
}

__device__ __forceinline__ void split_bf16(float v, __nv_bfloat16& h, __nv_bfloat16& l) {
    h = __float2bfloat16(v);
    l = __float2bfloat16(v - __bfloat162float(h));
}

// ---------------- zero per-launch accumulators ----------------
__global__ void zero_kernel() {
    int i = threadIdx.x;
    if (i < NE) { g_cnt[i] = 0; g_sumP[i] = 0.f; }
    if (i == 0) g_zsum = 0.f;
}

// ---------------- router ----------------
__global__ void router_kernel(const float* __restrict__ x, const float* __restrict__ rw) {
    int gw   = (blockIdx.x * blockDim.x + threadIdx.x) >> 5;
    int lane = threadIdx.x & 31;
    if (gw >= T_TOK) return;

    const float4* xp = (const float4*)(x + (size_t)gw * DIM);
    float4 xv[4];
#pragma unroll
    for (int i = 0; i < 4; i++) xv[i] = xp[lane * 4 + i];

    float logit[NE];
#pragma unroll
    for (int e = 0; e < NE; e++) {
        const float4* wp = (const float4*)(rw + (size_t)e * DIM);
        float acc = 0.f;
#pragma unroll
        for (int i = 0; i < 4; i++) {
            float4 w4 = wp[lane * 4 + i];
            acc += xv[i].x * w4.x + xv[i].y * w4.y + xv[i].z * w4.z + xv[i].w * w4.w;
        }
#pragma unroll
        for (int o = 16; o > 0; o >>= 1) acc += __shfl_xor_sync(0xffffffffu, acc, o);
        logit[e] = acc;
    }

    if (lane == 0) {
        float m = logit[0];
#pragma unroll
        for (int e = 1; e < NE; e++) m = fmaxf(m, logit[e]);
        float p[NE]; float se = 0.f;
#pragma unroll
        for (int e = 0; e < NE; e++) { p[e] = expf(logit[e] - m); se += p[e]; }
        float inv = 1.f / se;

        int i0 = 0; float v0 = -1.f;
#pragma unroll
        for (int e = 0; e < NE; e++) if (p[e] > v0) { v0 = p[e]; i0 = e; }
        int i1 = -1; float v1 = -1.f;
#pragma unroll
        for (int e = 0; e < NE; e++) if (e != i0 && p[e] > v1) { v1 = p[e]; i1 = e; }

        float s2 = v0 + v1;
        float w0 = v0 / s2, w1 = v1 / s2;

        int pos0 = atomicAdd(&g_cnt[i0], 1);
        g_list[i0 * T_TOK + pos0] = (gw << 1);
        g_wgt [i0 * T_TOK + pos0] = w0;
        int pos1 = atomicAdd(&g_cnt[i1], 1);
        g_list[i1 * T_TOK + pos1] = (gw << 1) | 1;
        g_wgt [i1 * T_TOK + pos1] = w1;

#pragma unroll
        for (int e = 0; e < NE; e++) atomicAdd(&g_sumP[e], p[e] * inv);
        float lse = m + logf(se);
        atomicAdd(&g_zsum, lse * lse);
    }
}

// ---------------- split x into bf16 hi/lo ----------------
__global__ void convert_x_kernel(const float* __restrict__ x) {
    int i = blockIdx.x * blockDim.x + threadIdx.x;    // one float4
    if (i >= T_TOK * DIM / 4) return;
    float4 v = ((const float4*)x)[i];
    __nv_bfloat16 h0,h1,h2,h3,l0,l1,l2,l3;
    split_bf16(v.x,h0,l0); split_bf16(v.y,h1,l1);
    split_bf16(v.z,h2,l2); split_bf16(v.w,h3,l3);
    ((__nv_bfloat162*)g_xh)[2*i]   = __nv_bfloat162(h0,h1);
    ((__nv_bfloat162*)g_xh)[2*i+1] = __nv_bfloat162(h2,h3);
    ((__nv_bfloat162*)g_xl)[2*i]   = __nv_bfloat162(l0,l1);
    ((__nv_bfloat162*)g_xl)[2*i+1] = __nv_bfloat162(l2,l3);
}

// ---------------- transpose + split weights:  in [E][R][C] -> out [E][C][R] ----------------
__global__ void transpose_split_kernel(const float* __restrict__ in, int which, int R, int C) {
    __shared__ float tile[32][33];
    size_t base = (size_t)blockIdx.z * R * C;
    int c0 = blockIdx.x * 32, r0 = blockIdx.y * 32;
    int tx = threadIdx.x, ty = threadIdx.y;
    __nv_bfloat16 *oh, *ol;
    if (which == 0)      { oh = g_gTh; ol = g_gTl; }
    else if (which == 1) { oh = g_uTh; ol = g_uTl; }
    else                 { oh = g_dTh; ol = g_dTl; }

    for (int i = ty; i < 32; i += 8)
        tile[i][tx] = in[base + (size_t)(r0 + i) * C + c0 + tx];
    __syncthreads();
    for (int i = ty; i < 32; i += 8) {
        float v = tile[tx][i];
        __nv_bfloat16 h, l;
        split_bf16(v, h, l);
        size_t o = base + (size_t)(c0 + i) * R + r0 + tx;
        oh[o] = h; ol[o] = l;
    }
}

// ================= Phase A: gate/up warp-MMA GEMM =================
// Block tile M=128 (gathered pairs) x N=64 (F cols), K staged 64/chunk, 8 chunks.
// smem row stride: 72 bf16 = 144B (conflict-free ldmatrix).
// Buffer layout (bytes, per buf): Ah 0, Al 18432, Bgh 36864, Bgl 46080, Buh 55296, Bul 64512. Buf=73728.
#define GU_SMEM (1024 + 2*73728)

__global__ void __launch_bounds__(256, 1) gateup_mma_kernel() {
    extern __shared__ char smem[];
    uint32_t sb = smem_u32(smem);
    int e = blockIdx.z;
    int cnt = g_cnt[e];
    int row0 = blockIdx.y * 128;
    if (row0 >= cnt) return;
    int col0 = blockIdx.x * 64;
    int tid = threadIdx.x, wid = tid >> 5, lid = tid & 31;
    int wm = wid >> 1, wn = wid & 1;
    int g = lid >> 2, t2 = (lid & 3) * 2;
    int* sTok = (int*)smem;

    for (int i = tid; i < 128; i += 256) {
        int r = row0 + i;
        sTok[i] = (r < cnt) ? g_list[e * T_TOK + r] : -1;
    }
    __syncthreads();

    const __nv_bfloat16* b0 = g_gTh + (size_t)e * FDIM * DIM;
    const __nv_bfloat16* b1 = g_gTl + (size_t)e * FDIM * DIM;
    const __nv_bfloat16* b2 = g_uTh + (size_t)e * FDIM * DIM;
    const __nv_bfloat16* b3 = g_uTl + (size_t)e * FDIM * DIM;

    float accg[2][4][4] = {}, accu[2][4][4] = {};

    auto stage = [&](int chunk) {
        int kt = chunk * 64;
        uint32_t bb = sb + 1024 + (chunk & 1) * 73728;
#pragma unroll
        for (int it = 0; it < 4; it++) {
            int t = tid + it * 256;
            int row = t >> 3, seg = t & 7;
            int entry = sTok[row];
            uint32_t bytes = (entry >= 0) ? 16u : 0u;
            size_t off = (size_t)((entry >= 0) ? (entry >> 1) : 0) * DIM + kt + seg * 8;
            uint32_t d = bb + row * 144 + seg * 16;
            cp16(d,         g_xh + off, bytes);
            cp16(d + 18432, g_xl + off, bytes);
        }
#pragma unroll
        for (int it = 0; it < 8; it++) {
            int t = tid + it * 256;
            int arr = t >> 9, u = t & 511, row = u >> 3, seg = u & 7;
            const __nv_bfloat16* src = (arr == 0) ? b0 : (arr == 1) ? b1 : (arr == 2) ? b2 : b3;
            cp16(bb + 36864 + arr * 9216 + row * 144 + seg * 16,
                 src + (size_t)(col0 + row) * DIM + kt + seg * 8, 16u);
        }
    };

    // ldmatrix per-lane byte offsets
    uint32_t laneA = (uint32_t)(((lid & 7) + ((lid >> 3) & 1) * 8) * 144 + ((lid >> 4) & 1) * 16);
    uint32_t laneB = (uint32_t)((lid & 7) * 144 + ((lid >> 3) & 1) * 16);

    stage(0); CP_COMMIT();
    for (int c = 0; c < 8; c++) {
        if (c + 1 < 8) { stage(c + 1); CP_COMMIT(); CP_WAIT1(); }
        else           { CP_WAIT0(); }
        __syncthreads();
        uint32_t bb = sb + 1024 + (c & 1) * 73728;
        uint32_t aBase = bb + (uint32_t)(wm * 32) * 144 + laneA;
        uint32_t bBase = bb + 36864 + (uint32_t)(wn * 32) * 144 + laneB;
#pragma unroll
        for (int kk = 0; kk < 4; kk++) {
            uint32_t ah[2][4], al[2][4];
#pragma unroll
            for (int mt = 0; mt < 2; mt++) {
                uint32_t aa = aBase + mt * (16 * 144) + kk * 32;
                ldsm_x4(ah[mt], aa);
                ldsm_x4(al[mt], aa + 18432);
            }
#pragma unroll
            for (int nt = 0; nt < 4; nt++) {
                uint32_t ba = bBase + nt * (8 * 144) + kk * 32;
                uint32_t bgh[2], bgl[2], buh[2], bul[2];
                ldsm_x2(bgh, ba);
                ldsm_x2(bgl, ba + 9216);
                ldsm_x2(buh, ba + 18432);
                ldsm_x2(bul, ba + 27648);
#pragma unroll
                for (int mt = 0; mt < 2; mt++) {
                    mma_bf16(accg[mt][nt], ah[mt], bgh);
                    mma_bf16(accg[mt][nt], ah[mt], bgl);
                    mma_bf16(accg[mt][nt], al[mt], bgh);
                    mma_bf16(accu[mt][nt], ah[mt], buh);
                    mma_bf16(accu[mt][nt], ah[mt], bul);
                    mma_bf16(accu[mt][nt], al[mt], buh);
                }
            }
        }
        __syncthreads();
    }

    // epilogue: h = silu(gate)*up, split to bf16 hi/lo
#pragma unroll
    for (int mt = 0; mt < 2; mt++) {
        int r0 = wm * 32 + mt * 16 + g;
        int e0 = sTok[r0], e1 = sTok[r0 + 8];
#pragma unroll
        for (int nt = 0; nt < 4; nt++) {
            int colg = col0 + wn * 32 + nt * 8 + t2;
            const float* dg = accg[mt][nt];
            const float* du = accu[mt][nt];
            if (e0 >= 0) {
                float h0 = du[0] * (dg[0] / (1.f + expf(-dg[0])));
                float h1 = du[1] * (dg[1] / (1.f + expf(-dg[1])));
                __nv_bfloat16 h0h, h0l, h1h, h1l;
                split_bf16(h0, h0h, h0l); split_bf16(h1, h1h, h1l);
                *(__nv_bfloat162*)(g_hh + (size_t)e0 * FDIM + colg) = __nv_bfloat162(h0h, h1h);
                *(__nv_bfloat162*)(g_hl + (size_t)e0 * FDIM + colg) = __nv_bfloat162(h0l, h1l);
            }
            if (e1 >= 0) {
                float h0 = du[2] * (dg[2] / (1.f + expf(-dg[2])));
                float h1 = du[3] * (dg[3] / (1.f + expf(-dg[3])));
                __nv_bfloat16 h0h, h0l, h1h, h1l;
                split_bf16(h0, h0h, h0l); split_bf16(h1, h1h, h1l);
                *(__nv_bfloat162*)(g_hh + (size_t)e1 * FDIM + colg) = __nv_bfloat162(h0h, h1h);
                *(__nv_bfloat162*)(g_hl + (size_t)e1 * FDIM + colg) = __nv_bfloat162(h0l, h1l);
            }
        }
    }
}

// ================= Phase B: down warp-MMA GEMM =================
// Block tile M=128 x N=64 (D cols), K=1024 staged 64/chunk, 16 chunks.
// Buf layout: Ah 0, Al 18432, Bh 36864, Bl 46080. Buf=55296.
#define DN_SMEM (1024 + 2*55296)

__global__ void __launch_bounds__(256, 1) down_mma_kernel() {
    extern __shared__ char smem[];
    uint32_t sb = smem_u32(smem);
    int e = blockIdx.z;
    int cnt = g_cnt[e];
    int row0 = blockIdx.y * 128;
    if (row0 >= cnt) return;
    int col0 = blockIdx.x * 64;
    int tid = threadIdx.x, wid = tid >> 5, lid = tid & 31;
    int wm = wid >> 1, wn = wid & 1;
    int g = lid >> 2, t2 = (lid & 3) * 2;
    int*   sTok = (int*)smem;
    float* sW   = (float*)(smem + 512);

    for (int i = tid; i < 128; i += 256) {
        int r = row0 + i;
        sTok[i] = (r < cnt) ? g_list[e * T_TOK + r] : -1;
        sW[i]   = (r < cnt) ? g_wgt [e * T_TOK + r] : 0.f;
    }
    __syncthreads();

    const __nv_bfloat16* dh = g_dTh + (size_t)e * DIM * FDIM;
    const __nv_bfloat16* dl = g_dTl + (size_t)e * DIM * FDIM;

    float acc[2][4][4] = {};

    auto stage = [&](int chunk) {
        int kt = chunk * 64;
        uint32_t bb = sb + 1024 + (chunk & 1) * 55296;
#pragma unroll
        for (int it = 0; it < 8; it++) {
            int t = tid + it * 256;
            int arr = t >> 10, u = t & 1023, row = u >> 3, seg = u & 7;
            int entry = sTok[row];
            uint32_t bytes = (entry >= 0) ? 16u : 0u;
            const __nv_bfloat16* src = (arr ? g_hl : g_hh)
                + (size_t)((entry >= 0) ? entry : 0) * FDIM + kt + seg * 8;
            cp16(bb + arr * 18432 + row * 144 + seg * 16, src, bytes);
        }
#pragma unroll
        for (int it = 0; it < 4; it++) {
            int t = tid + it * 256;
            int arr = t >> 9, u = t & 511, row = u >> 3, seg = u & 7;
            const __nv_bfloat16* src = (arr ? dl : dh)
                + (size_t)(col0 + row) * FDIM + kt + seg * 8;
            cp16(bb + 36864 + arr * 9216 + row * 144 + seg * 16, src, 16u);
        }
    };

    uint32_t laneA = (uint32_t)(((lid & 7) + ((lid >> 3) & 1) * 8) * 144 + ((lid >> 4) & 1) * 16);
    uint32_t laneB = (uint32_t)((lid & 7) * 144 + ((lid >> 3) & 1) * 16);

    stage(0); CP_COMMIT();
    for (int c = 0; c < 16; c++) {
        if (c + 1 < 16) { stage(c + 1); CP_COMMIT(); CP_WAIT1(); }
        else            { CP_WAIT0(); }
        __syncthreads();
        uint32_t bb = sb + 1024 + (c & 1) * 55296;
        uint32_t aBase = bb + (uint32_t)(wm * 32) * 144 + laneA;
        uint32_t bBase = bb + 36864 + (uint32_t)(wn * 32) * 144 + laneB;
#pragma unroll
        for (int kk = 0; kk < 4; kk++) {
            uint32_t ah[2][4], al[2][4];
#pragma unroll
            for (int mt = 0; mt < 2; mt++) {
                uint32_t aa = aBase + mt * (16 * 144) + kk * 32;
                ldsm_x4(ah[mt], aa);
                ldsm_x4(al[mt], aa + 18432);
            }
#pragma unroll
            for (int nt = 0; nt < 4; nt++) {
                uint32_t ba = bBase + nt * (8 * 144) + kk * 32;
                uint32_t bh[2], bl[2];
                ldsm_x2(bh, ba);
                ldsm_x2(bl, ba + 9216);
#pragma unroll
                for (int mt = 0; mt < 2; mt++) {
                    mma_bf16(acc[mt][nt], ah[mt], bh);
                    mma_bf16(acc[mt][nt], ah[mt], bl);
                    mma_bf16(acc[mt][nt], al[mt], bh);
                }
            }
        }
        __syncthreads();
    }

    // epilogue: scale by combine weight, write per-pair slot
#pragma unroll
    for (int mt = 0; mt < 2; mt++) {
        int r0 = wm * 32 + mt * 16 + g;
        int e0 = sTok[r0], e1 = sTok[r0 + 8];
        float w0 = sW[r0], w1 = sW[r0 + 8];
#pragma unroll
        for (int nt = 0; nt < 4; nt++) {
            int cg = col0 + wn * 32 + nt * 8 + t2;
            const float* d = acc[mt][nt];
            if (e0 >= 0) {
                float2 o = make_float2(w0 * d[0], w0 * d[1]);
                *(float2*)(g_pout + (size_t)e0 * DIM + cg) = o;
            }
            if (e1 >= 0) {
                float2 o = make_float2(w1 * d[2], w1 * d[3]);
                *(float2*)(g_pout + (size_t)e1 * DIM + cg) = o;
            }
        }
    }
}

// ---------------- combine the two pair slots per token ----------------
__global__ void combine_kernel(float* __restrict__ out) {
    int i = blockIdx.x * blockDim.x + threadIdx.x;
    const int N4 = T_TOK * DIM / 4;
    const int D4 = DIM / 4;
    if (i >= N4) return;
    int t = i / D4, c = i % D4;
    const float4* p = (const float4*)g_pout;
    float4 a = p[(size_t)(2 * t) * D4 + c];
    float4 b = p[(size_t)(2 * t + 1) * D4 + c];
    ((float4*)out)[i] = make_float4(a.x + b.x, a.y + b.y, a.z + b.z, a.w + b.w);
}

// ---------------- aux loss ----------------
__global__ void finalize_kernel(float* __restrict__ out, int out_size) {
    float lb = 0.f;
#pragma unroll
    for (int e = 0; e < NE; e++)
        lb += ((float)g_cnt[e] / (float)NPAIR) * (g_sumP[e] / (float)T_TOK);
    float aux = 0.01f * (float)NE * lb + 0.001f * (g_zsum / (float)T_TOK);
    out[out_size - 1] = aux;
}

// ---------------- launch ----------------
extern "C" void kernel_launch(void* const* d_in, const int* in_sizes, int n_in,
                              void* d_out, int out_size) {
    const float* x  = (const float*)d_in[0];
    const float* rw = (const float*)d_in[1];
    const float* gw = (const float*)d_in[2];
    const float* uw = (const float*)d_in[3];
    const float* dw = (const float*)d_in[4];
    float* out = (float*)d_out;

    cudaFuncSetAttribute(gateup_mma_kernel, cudaFuncAttributeMaxDynamicSharedMemorySize, GU_SMEM);
    cudaFuncSetAttribute(down_mma_kernel,   cudaFuncAttributeMaxDynamicSharedMemorySize, DN_SMEM);

    zero_kernel<<<1, 32>>>();
    convert_x_kernel<<<(T_TOK * DIM / 4 + 255) / 256, 256>>>(x);
    transpose_split_kernel<<<dim3(FDIM / 32, DIM / 32, NE), dim3(32, 8)>>>(gw, 0, DIM, FDIM);
    transpose_split_kernel<<<dim3(FDIM / 32, DIM / 32, NE), dim3(32, 8)>>>(uw, 1, DIM, FDIM);
    transpose_split_kernel<<<dim3(DIM / 32, FDIM / 32, NE), dim3(32, 8)>>>(dw, 2, FDIM, DIM);
    router_kernel<<<T_TOK / 4, 128>>>(x, rw);
    gateup_mma_kernel<<<dim3(FDIM / 64, T_TOK / 128, NE), 256, GU_SMEM>>>();
    down_mma_kernel<<<dim3(DIM / 64, T_TOK / 128, NE), 256, DN_SMEM>>>();
    combine_kernel<<<(T_TOK * DIM / 4 + 255) / 256, 256>>>(out);
    finalize_kernel<<<1, 1>>>(out, out_size);
}

// round 8
// speedup vs baseline: 1.7411x; 1.0388x over previous
#include <cuda_runtime.h>
#include <cuda_bf16.h>
#include <math.h>
#include <stdint.h>

// Problem constants (fixed shapes)
#define T_TOK 4096
#define DIM   512
#define FDIM  1024
#define NE    8
#define TOPK  2
#define NPAIR (T_TOK*TOPK)

// ---------------- device scratch (static; no runtime allocation) ----------------
__device__ int   g_cnt[NE];
__device__ int   g_list[NE*T_TOK];   // packed (token<<1)|k
__device__ float g_wgt [NE*T_TOK];
__device__ float g_sumP[NE];
__device__ float g_zsum;

// bf16 hi/lo splits (NATURAL layouts — no transpose)
__device__ __nv_bfloat16 g_xh[(size_t)T_TOK*DIM];
__device__ __nv_bfloat16 g_xl[(size_t)T_TOK*DIM];
__device__ __nv_bfloat16 g_gh[(size_t)NE*DIM*FDIM];  // gate [E][D][F]
__device__ __nv_bfloat16 g_gl[(size_t)NE*DIM*FDIM];
__device__ __nv_bfloat16 g_uh[(size_t)NE*DIM*FDIM];  // up   [E][D][F]
__device__ __nv_bfloat16 g_ul[(size_t)NE*DIM*FDIM];
__device__ __nv_bfloat16 g_dh[(size_t)NE*FDIM*DIM];  // down [E][F][D]
__device__ __nv_bfloat16 g_dl[(size_t)NE*FDIM*DIM];
__device__ __nv_bfloat16 g_hh[(size_t)NPAIR*FDIM];   // hidden hi (K-major for phase B)
__device__ __nv_bfloat16 g_hl[(size_t)NPAIR*FDIM];
__device__ float g_pout[(size_t)NPAIR*DIM];

// ================= PTX helpers (family-portable: sm_80+) =================
__device__ __forceinline__ uint32_t smem_u32(const void* p) {
    uint32_t a;
    asm("{ .reg .u64 t; cvta.to.shared.u64 t, %1; cvt.u32.u64 %0, t; }" : "=r"(a) : "l"(p));
    return a;
}
__device__ __forceinline__ void cp16(uint32_t dst, const void* src, uint32_t bytes) {
    asm volatile("cp.async.cg.shared.global [%0], [%1], 16, %2;"
                 :: "r"(dst), "l"(src), "r"(bytes) : "memory");
}
#define CP_COMMIT() asm volatile("cp.async.commit_group;" ::: "memory")
#define CP_WAITG(n) asm volatile("cp.async.wait_group %0;" :: "n"(n) : "memory")

__device__ __forceinline__ void ldsm_x4(uint32_t* r, uint32_t addr) {
    asm volatile("ldmatrix.sync.aligned.m8n8.x4.shared.b16 {%0,%1,%2,%3}, [%4];"
        : "=r"(r[0]), "=r"(r[1]), "=r"(r[2]), "=r"(r[3]) : "r"(addr));
}
__device__ __forceinline__ void ldsm_x4_t(uint32_t* r, uint32_t addr) {
    asm volatile("ldmatrix.sync.aligned.m8n8.x4.trans.shared.b16 {%0,%1,%2,%3}, [%4];"
        : "=r"(r[0]), "=r"(r[1]), "=r"(r[2]), "=r"(r[3]) : "r"(addr));
}
__device__ __forceinline__ void mma_bf16(float* d, const uint32_t* a, const uint32_t* b) {
    asm volatile("mma.sync.aligned.m16n8k16.row.col.f32.bf16.bf16.f32 "
        "{%0,%1,%2,%3}, {%4,%5,%6,%7}, {%8,%9}, {%0,%1,%2,%3};"
        : "+f"(d[0]), "+f"(d[1]), "+f"(d[2]), "+f"(d[3])
        : "r"(a[0]), "r"(a[1]), "r"(a[2]), "r"(a[3]), "r"(b[0]), "r"(b[1]));
}

__device__ __forceinline__ void split_bf16(float v, __nv_bfloat16& h, __nv_bfloat16& l) {
    h = __float2bfloat16(v);
    l = __float2bfloat16(v - __bfloat162float(h));
}

// ---------------- zero per-launch accumulators ----------------
__global__ void zero_kernel() {
    int i = threadIdx.x;
    if (i < NE) { g_cnt[i] = 0; g_sumP[i] = 0.f; }
    if (i == 0) g_zsum = 0.f;
}

// ---------------- router ----------------
__global__ void router_kernel(const float* __restrict__ x, const float* __restrict__ rw) {
    int gw   = (blockIdx.x * blockDim.x + threadIdx.x) >> 5;
    int lane = threadIdx.x & 31;
    if (gw >= T_TOK) return;

    const float4* xp = (const float4*)(x + (size_t)gw * DIM);
    float4 xv[4];
#pragma unroll
    for (int i = 0; i < 4; i++) xv[i] = xp[lane * 4 + i];

    float logit[NE];
#pragma unroll
    for (int e = 0; e < NE; e++) {
        const float4* wp = (const float4*)(rw + (size_t)e * DIM);
        float acc = 0.f;
#pragma unroll
        for (int i = 0; i < 4; i++) {
            float4 w4 = wp[lane * 4 + i];
            acc += xv[i].x * w4.x + xv[i].y * w4.y + xv[i].z * w4.z + xv[i].w * w4.w;
        }
#pragma unroll
        for (int o = 16; o > 0; o >>= 1) acc += __shfl_xor_sync(0xffffffffu, acc, o);
        logit[e] = acc;
    }

    if (lane == 0) {
        float m = logit[0];
#pragma unroll
        for (int e = 1; e < NE; e++) m = fmaxf(m, logit[e]);
        float p[NE]; float se = 0.f;
#pragma unroll
        for (int e = 0; e < NE; e++) { p[e] = expf(logit[e] - m); se += p[e]; }
        float inv = 1.f / se;

        int i0 = 0; float v0 = -1.f;
#pragma unroll
        for (int e = 0; e < NE; e++) if (p[e] > v0) { v0 = p[e]; i0 = e; }
        int i1 = -1; float v1 = -1.f;
#pragma unroll
        for (int e = 0; e < NE; e++) if (e != i0 && p[e] > v1) { v1 = p[e]; i1 = e; }

        float s2 = v0 + v1;
        float w0 = v0 / s2, w1 = v1 / s2;

        int pos0 = atomicAdd(&g_cnt[i0], 1);
        g_list[i0 * T_TOK + pos0] = (gw << 1);
        g_wgt [i0 * T_TOK + pos0] = w0;
        int pos1 = atomicAdd(&g_cnt[i1], 1);
        g_list[i1 * T_TOK + pos1] = (gw << 1) | 1;
        g_wgt [i1 * T_TOK + pos1] = w1;

#pragma unroll
        for (int e = 0; e < NE; e++) atomicAdd(&g_sumP[e], p[e] * inv);
        float lse = m + logf(se);
        atomicAdd(&g_zsum, lse * lse);
    }
}

// ---------------- split x into bf16 hi/lo ----------------
__global__ void convert_x_kernel(const float* __restrict__ x) {
    int i = blockIdx.x * blockDim.x + threadIdx.x;
    if (i >= T_TOK * DIM / 4) return;
    float4 v = ((const float4*)x)[i];
    __nv_bfloat16 h0,h1,h2,h3,l0,l1,l2,l3;
    split_bf16(v.x,h0,l0); split_bf16(v.y,h1,l1);
    split_bf16(v.z,h2,l2); split_bf16(v.w,h3,l3);
    ((__nv_bfloat162*)g_xh)[2*i]   = __nv_bfloat162(h0,h1);
    ((__nv_bfloat162*)g_xh)[2*i+1] = __nv_bfloat162(h2,h3);
    ((__nv_bfloat162*)g_xl)[2*i]   = __nv_bfloat162(l0,l1);
    ((__nv_bfloat162*)g_xl)[2*i+1] = __nv_bfloat162(l2,l3);
}

// ---------------- streaming hi/lo split of all weights (no transpose) ----------------
#define WPER (NE*DIM*FDIM/4)   // float4s per tensor = 1048576
__global__ void split_weights_kernel(const float* __restrict__ gw,
                                     const float* __restrict__ uw,
                                     const float* __restrict__ dw) {
    int i = blockIdx.x * blockDim.x + threadIdx.x;
    if (i >= 3 * WPER) return;
    int which = i / WPER, j = i - which * WPER;
    const float* src = (which == 0) ? gw : (which == 1) ? uw : dw;
    __nv_bfloat16* oh = (which == 0) ? g_gh : (which == 1) ? g_uh : g_dh;
    __nv_bfloat16* ol = (which == 0) ? g_gl : (which == 1) ? g_ul : g_dl;
    float4 v = ((const float4*)src)[j];
    __nv_bfloat16 h0,h1,h2,h3,l0,l1,l2,l3;
    split_bf16(v.x,h0,l0); split_bf16(v.y,h1,l1);
    split_bf16(v.z,h2,l2); split_bf16(v.w,h3,l3);
    ((__nv_bfloat162*)oh)[2*(size_t)j]   = __nv_bfloat162(h0,h1);
    ((__nv_bfloat162*)oh)[2*(size_t)j+1] = __nv_bfloat162(h2,h3);
    ((__nv_bfloat162*)ol)[2*(size_t)j]   = __nv_bfloat162(l0,l1);
    ((__nv_bfloat162*)ol)[2*(size_t)j+1] = __nv_bfloat162(l2,l3);
}

// ================= Phase A: gate/up warp-MMA GEMM =================
// Block tile M=128 (gathered pairs) x N=64 (F cols), K chunks of 64 (8 chunks), 3-stage pipeline.
// smem row stride 144B. Per stage: Ah 0, Al 18432, Bgh 36864, Bgl 46080, Buh 55296, Bul 64512; 73728 B.
#define GU_STG  73728
#define GU_SMEM (1024 + 3*GU_STG)

__global__ void __launch_bounds__(256, 1) gateup_mma_kernel() {
    extern __shared__ char smem[];
    uint32_t sb = smem_u32(smem);
    int e = blockIdx.z;
    int cnt = g_cnt[e];
    int row0 = blockIdx.y * 128;
    if (row0 >= cnt) return;
    int col0 = blockIdx.x * 64;
    int tid = threadIdx.x, wid = tid >> 5, lid = tid & 31;
    int wm = wid >> 1, wn = wid & 1;
    int g = lid >> 2, t2 = (lid & 3) * 2;
    int* sTok = (int*)smem;

    for (int i = tid; i < 128; i += 256) {
        int r = row0 + i;
        sTok[i] = (r < cnt) ? g_list[e * T_TOK + r] : -1;
    }
    __syncthreads();

    const __nv_bfloat16* b0 = g_gh + (size_t)e * DIM * FDIM;   // [D][F]
    const __nv_bfloat16* b1 = g_gl + (size_t)e * DIM * FDIM;
    const __nv_bfloat16* b2 = g_uh + (size_t)e * DIM * FDIM;
    const __nv_bfloat16* b3 = g_ul + (size_t)e * DIM * FDIM;

    float accg[2][4][4] = {}, accu[2][4][4] = {};

    auto stage = [&](int chunk) {
        int kt = chunk * 64;
        uint32_t bb = sb + 1024 + (uint32_t)(chunk % 3) * GU_STG;
        // A gathered rows [128 M][64 K], K-major
#pragma unroll
        for (int it = 0; it < 4; it++) {
            int t = tid + it * 256;
            int row = t >> 3, seg = t & 7;
            int entry = sTok[row];
            uint32_t bytes = (entry >= 0) ? 16u : 0u;
            size_t off = (size_t)((entry >= 0) ? (entry >> 1) : 0) * DIM + kt + seg * 8;
            uint32_t d = bb + row * 144 + seg * 16;
            cp16(d,         g_xh + off, bytes);
            cp16(d + 18432, g_xl + off, bytes);
        }
        // B natural layout [64 K][64 N] rows from [D][F]
#pragma unroll
        for (int it = 0; it < 8; it++) {
            int t = tid + it * 256;
            int arr = t >> 9, u = t & 511, row = u >> 3, seg = u & 7;
            const __nv_bfloat16* src = (arr == 0) ? b0 : (arr == 1) ? b1 : (arr == 2) ? b2 : b3;
            cp16(bb + 36864 + arr * 9216 + row * 144 + seg * 16,
                 src + (size_t)(kt + row) * FDIM + col0 + seg * 8, 16u);
        }
    };

    // lane offset shared by A (non-trans) and B (trans): rows via (lid&7)+8*((lid>>3)&1), +16B via bit4
    uint32_t laneO = (uint32_t)(((lid & 7) + ((lid >> 3) & 1) * 8) * 144 + ((lid >> 4) & 1) * 16);

    stage(0); CP_COMMIT();
    stage(1); CP_COMMIT();
    for (int c = 0; c < 8; c++) {
        if (c + 2 < 8) { stage(c + 2); CP_COMMIT(); CP_WAITG(2); }
        else           { CP_WAITG(0); }
        __syncthreads();
        uint32_t bb = sb + 1024 + (uint32_t)(c % 3) * GU_STG;
        uint32_t aBase = bb + (uint32_t)(wm * 32) * 144 + laneO;
        uint32_t bBase = bb + 36864 + laneO + (uint32_t)(wn * 32) * 2;
#pragma unroll
        for (int kk = 0; kk < 4; kk++) {
            uint32_t ah[2][4], al[2][4];
#pragma unroll
            for (int mt = 0; mt < 2; mt++) {
                uint32_t aa = aBase + mt * (16 * 144) + kk * 32;
                ldsm_x4(ah[mt], aa);
                ldsm_x4(al[mt], aa + 18432);
            }
#pragma unroll
            for (int nt = 0; nt < 2; nt++) {
                uint32_t ba = bBase + kk * (16 * 144) + nt * 32;
                uint32_t bgh[4], bgl[4], buh[4], bul[4];
                ldsm_x4_t(bgh, ba);
                ldsm_x4_t(bgl, ba + 9216);
                ldsm_x4_t(buh, ba + 18432);
                ldsm_x4_t(bul, ba + 27648);
#pragma unroll
                for (int h = 0; h < 2; h++) {
                    int n8 = nt * 2 + h;
#pragma unroll
                    for (int mt = 0; mt < 2; mt++) {
                        mma_bf16(accg[mt][n8], ah[mt], bgh + h * 2);
                        mma_bf16(accg[mt][n8], ah[mt], bgl + h * 2);
                        mma_bf16(accg[mt][n8], al[mt], bgh + h * 2);
                        mma_bf16(accu[mt][n8], ah[mt], buh + h * 2);
                        mma_bf16(accu[mt][n8], ah[mt], bul + h * 2);
                        mma_bf16(accu[mt][n8], al[mt], buh + h * 2);
                    }
                }
            }
        }
        __syncthreads();
    }

    // epilogue: h = silu(gate)*up, split to bf16 hi/lo
#pragma unroll
    for (int mt = 0; mt < 2; mt++) {
        int r0 = wm * 32 + mt * 16 + g;
        int e0 = sTok[r0], e1 = sTok[r0 + 8];
#pragma unroll
        for (int nt = 0; nt < 4; nt++) {
            int colg = col0 + wn * 32 + nt * 8 + t2;
            const float* dg = accg[mt][nt];
            const float* du = accu[mt][nt];
            if (e0 >= 0) {
                float h0 = du[0] * (dg[0] / (1.f + expf(-dg[0])));
                float h1 = du[1] * (dg[1] / (1.f + expf(-dg[1])));
                __nv_bfloat16 h0h, h0l, h1h, h1l;
                split_bf16(h0, h0h, h0l); split_bf16(h1, h1h, h1l);
                *(__nv_bfloat162*)(g_hh + (size_t)e0 * FDIM + colg) = __nv_bfloat162(h0h, h1h);
                *(__nv_bfloat162*)(g_hl + (size_t)e0 * FDIM + colg) = __nv_bfloat162(h0l, h1l);
            }
            if (e1 >= 0) {
                float h0 = du[2] * (dg[2] / (1.f + expf(-dg[2])));
                float h1 = du[3] * (dg[3] / (1.f + expf(-dg[3])));
                __nv_bfloat16 h0h, h0l, h1h, h1l;
                split_bf16(h0, h0h, h0l); split_bf16(h1, h1h, h1l);
                *(__nv_bfloat162*)(g_hh + (size_t)e1 * FDIM + colg) = __nv_bfloat162(h0h, h1h);
                *(__nv_bfloat162*)(g_hl + (size_t)e1 * FDIM + colg) = __nv_bfloat162(h0l, h1l);
            }
        }
    }
}

// ================= Phase B: down warp-MMA GEMM =================
// Block tile M=128 x N=64 (D cols), K=1024 in 16 chunks of 64, 4-stage pipeline.
// Per stage: Ah 0, Al 18432, Bh 36864, Bl 46080; 55296 B.
#define DN_STG  55296
#define DN_SMEM (1024 + 4*DN_STG)

__global__ void __launch_bounds__(256, 1) down_mma_kernel() {
    extern __shared__ char smem[];
    uint32_t sb = smem_u32(smem);
    int e = blockIdx.z;
    int cnt = g_cnt[e];
    int row0 = blockIdx.y * 128;
    if (row0 >= cnt) return;
    int col0 = blockIdx.x * 64;
    int tid = threadIdx.x, wid = tid >> 5, lid = tid & 31;
    int wm = wid >> 1, wn = wid & 1;
    int g = lid >> 2, t2 = (lid & 3) * 2;
    int*   sTok = (int*)smem;
    float* sW   = (float*)(smem + 512);

    for (int i = tid; i < 128; i += 256) {
        int r = row0 + i;
        sTok[i] = (r < cnt) ? g_list[e * T_TOK + r] : -1;
        sW[i]   = (r < cnt) ? g_wgt [e * T_TOK + r] : 0.f;
    }
    __syncthreads();

    const __nv_bfloat16* dh = g_dh + (size_t)e * FDIM * DIM;   // [F][D]
    const __nv_bfloat16* dl = g_dl + (size_t)e * FDIM * DIM;

    float acc[2][4][4] = {};

    auto stage = [&](int chunk) {
        int kt = chunk * 64;
        uint32_t bb = sb + 1024 + (uint32_t)(chunk & 3) * DN_STG;
#pragma unroll
        for (int it = 0; it < 8; it++) {
            int t = tid + it * 256;
            int arr = t >> 10, u = t & 1023, row = u >> 3, seg = u & 7;
            int entry = sTok[row];
            uint32_t bytes = (entry >= 0) ? 16u : 0u;
            const __nv_bfloat16* src = (arr ? g_hl : g_hh)
                + (size_t)((entry >= 0) ? entry : 0) * FDIM + kt + seg * 8;
            cp16(bb + arr * 18432 + row * 144 + seg * 16, src, bytes);
        }
        // B natural layout [64 K][64 N] rows from [F][D]
#pragma unroll
        for (int it = 0; it < 4; it++) {
            int t = tid + it * 256;
            int arr = t >> 9, u = t & 511, row = u >> 3, seg = u & 7;
            const __nv_bfloat16* src = (arr ? dl : dh)
                + (size_t)(kt + row) * DIM + col0 + seg * 8;
            cp16(bb + 36864 + arr * 9216 + row * 144 + seg * 16, src, 16u);
        }
    };

    uint32_t laneO = (uint32_t)(((lid & 7) + ((lid >> 3) & 1) * 8) * 144 + ((lid >> 4) & 1) * 16);

    stage(0); CP_COMMIT();
    stage(1); CP_COMMIT();
    stage(2); CP_COMMIT();
    for (int c = 0; c < 16; c++) {
        if (c + 3 < 16) { stage(c + 3); CP_COMMIT(); CP_WAITG(3); }
        else            { CP_WAITG(0); }
        __syncthreads();
        uint32_t bb = sb + 1024 + (uint32_t)(c & 3) * DN_STG;
        uint32_t aBase = bb + (uint32_t)(wm * 32) * 144 + laneO;
        uint32_t bBase = bb + 36864 + laneO + (uint32_t)(wn * 32) * 2;
#pragma unroll
        for (int kk = 0; kk < 4; kk++) {
            uint32_t ah[2][4], al[2][4];
#pragma unroll
            for (int mt = 0; mt < 2; mt++) {
                uint32_t aa = aBase + mt * (16 * 144) + kk * 32;
                ldsm_x4(ah[mt], aa);
                ldsm_x4(al[mt], aa + 18432);
            }
#pragma unroll
            for (int nt = 0; nt < 2; nt++) {
                uint32_t ba = bBase + kk * (16 * 144) + nt * 32;
                uint32_t bh[4], bl[4];
                ldsm_x4_t(bh, ba);
                ldsm_x4_t(bl, ba + 9216);
#pragma unroll
                for (int h = 0; h < 2; h++) {
                    int n8 = nt * 2 + h;
#pragma unroll
                    for (int mt = 0; mt < 2; mt++) {
                        mma_bf16(acc[mt][n8], ah[mt], bh + h * 2);
                        mma_bf16(acc[mt][n8], ah[mt], bl + h * 2);
                        mma_bf16(acc[mt][n8], al[mt], bh + h * 2);
                    }
                }
            }
        }
        __syncthreads();
    }

    // epilogue: scale by combine weight, write per-pair slot
#pragma unroll
    for (int mt = 0; mt < 2; mt++) {
        int r0 = wm * 32 + mt * 16 + g;
        int e0 = sTok[r0], e1 = sTok[r0 + 8];
        float w0 = sW[r0], w1 = sW[r0 + 8];
#pragma unroll
        for (int nt = 0; nt < 4; nt++) {
            int cg = col0 + wn * 32 + nt * 8 + t2;
            const float* d = acc[mt][nt];
            if (e0 >= 0) {
                float2 o = make_float2(w0 * d[0], w0 * d[1]);
                *(float2*)(g_pout + (size_t)e0 * DIM + cg) = o;
            }
            if (e1 >= 0) {
                float2 o = make_float2(w1 * d[2], w1 * d[3]);
                *(float2*)(g_pout + (size_t)e1 * DIM + cg) = o;
            }
        }
    }
}

// ---------------- combine the two pair slots per token ----------------
__global__ void combine_kernel(float* __restrict__ out) {
    int i = blockIdx.x * blockDim.x + threadIdx.x;
    const int N4 = T_TOK * DIM / 4;
    const int D4 = DIM / 4;
    if (i >= N4) return;
    int t = i / D4, c = i % D4;
    const float4* p = (const float4*)g_pout;
    float4 a = p[(size_t)(2 * t) * D4 + c];
    float4 b = p[(size_t)(2 * t + 1) * D4 + c];
    ((float4*)out)[i] = make_float4(a.x + b.x, a.y + b.y, a.z + b.z, a.w + b.w);
}

// ---------------- aux loss ----------------
__global__ void finalize_kernel(float* __restrict__ out, int out_size) {
    float lb = 0.f;
#pragma unroll
    for (int e = 0; e < NE; e++)
        lb += ((float)g_cnt[e] / (float)NPAIR) * (g_sumP[e] / (float)T_TOK);
    float aux = 0.01f * (float)NE * lb + 0.001f * (g_zsum / (float)T_TOK);
    out[out_size - 1] = aux;
}

// ---------------- launch ----------------
extern "C" void kernel_launch(void* const* d_in, const int* in_sizes, int n_in,
                              void* d_out, int out_size) {
    const float* x  = (const float*)d_in[0];
    const float* rw = (const float*)d_in[1];
    const float* gw = (const float*)d_in[2];
    const float* uw = (const float*)d_in[3];
    const float* dw = (const float*)d_in[4];
    float* out = (float*)d_out;

    cudaFuncSetAttribute(gateup_mma_kernel, cudaFuncAttributeMaxDynamicSharedMemorySize, GU_SMEM);
    cudaFuncSetAttribute(down_mma_kernel,   cudaFuncAttributeMaxDynamicSharedMemorySize, DN_SMEM);

    zero_kernel<<<1, 32>>>();
    convert_x_kernel<<<(T_TOK * DIM / 4 + 255) / 256, 256>>>(x);
    split_weights_kernel<<<(3 * WPER + 255) / 256, 256>>>(gw, uw, dw);
    router_kernel<<<T_TOK / 4, 128>>>(x, rw);
    gateup_mma_kernel<<<dim3(FDIM / 64, T_TOK / 128, NE), 256, GU_SMEM>>>();
    down_mma_kernel<<<dim3(DIM / 64, T_TOK / 128, NE), 256, DN_SMEM>>>();
    combine_kernel<<<(T_TOK * DIM / 4 + 255) / 256, 256>>>(out);
    finalize_kernel<<<1, 1>>>(out, out_size);
}

// round 9
// speedup vs baseline: 1.9747x; 1.1342x over previous
#include <cuda_runtime.h>
#include <cuda_bf16.h>
#include <math.h>
#include <stdint.h>

// Problem constants (fixed shapes)
#define T_TOK 4096
#define DIM   512
#define FDIM  1024
#define NE    8
#define TOPK  2
#define NPAIR (T_TOK*TOPK)

// ---------------- device scratch (static; no runtime allocation) ----------------
__device__ int   g_cnt[NE];
__device__ int   g_list[NE*T_TOK];   // packed (token<<1)|k
__device__ float g_wgt [NE*T_TOK];
__device__ float g_sumP[NE];
__device__ float g_zsum;

// bf16 hi/lo splits (NATURAL layouts — no transpose)
__device__ __nv_bfloat16 g_xh[(size_t)T_TOK*DIM];
__device__ __nv_bfloat16 g_xl[(size_t)T_TOK*DIM];
__device__ __nv_bfloat16 g_gh[(size_t)NE*DIM*FDIM];  // gate [E][D][F]
__device__ __nv_bfloat16 g_gl[(size_t)NE*DIM*FDIM];
__device__ __nv_bfloat16 g_uh[(size_t)NE*DIM*FDIM];  // up   [E][D][F]
__device__ __nv_bfloat16 g_ul[(size_t)NE*DIM*FDIM];
__device__ __nv_bfloat16 g_dh[(size_t)NE*FDIM*DIM];  // down [E][F][D]
__device__ __nv_bfloat16 g_dl[(size_t)NE*FDIM*DIM];
__device__ __nv_bfloat16 g_hh[(size_t)NPAIR*FDIM];   // hidden hi (K-major for phase B)
__device__ __nv_bfloat16 g_hl[(size_t)NPAIR*FDIM];
__device__ float g_pout[(size_t)NPAIR*DIM];

// ================= PTX helpers (family-portable: sm_80+) =================
__device__ __forceinline__ uint32_t smem_u32(const void* p) {
    uint32_t a;
    asm("{ .reg .u64 t; cvta.to.shared.u64 t, %1; cvt.u32.u64 %0, t; }" : "=r"(a) : "l"(p));
    return a;
}
__device__ __forceinline__ void cp16(uint32_t dst, const void* src, uint32_t bytes) {
    asm volatile("cp.async.cg.shared.global [%0], [%1], 16, %2;"
                 :: "r"(dst), "l"(src), "r"(bytes) : "memory");
}
#define CP_COMMIT() asm volatile("cp.async.commit_group;" ::: "memory")
#define CP_WAITG(n) asm volatile("cp.async.wait_group %0;" :: "n"(n) : "memory")

__device__ __forceinline__ void ldsm_x4(uint32_t* r, uint32_t addr) {
    asm volatile("ldmatrix.sync.aligned.m8n8.x4.shared.b16 {%0,%1,%2,%3}, [%4];"
        : "=r"(r[0]), "=r"(r[1]), "=r"(r[2]), "=r"(r[3]) : "r"(addr));
}
__device__ __forceinline__ void ldsm_x4_t(uint32_t* r, uint32_t addr) {
    asm volatile("ldmatrix.sync.aligned.m8n8.x4.trans.shared.b16 {%0,%1,%2,%3}, [%4];"
        : "=r"(r[0]), "=r"(r[1]), "=r"(r[2]), "=r"(r[3]) : "r"(addr));
}
__device__ __forceinline__ void mma_bf16(float* d, const uint32_t* a, const uint32_t* b) {
    asm volatile("mma.sync.aligned.m16n8k16.row.col.f32.bf16.bf16.f32 "
        "{%0,%1,%2,%3}, {%4,%5,%6,%7}, {%8,%9}, {%0,%1,%2,%3};"
        : "+f"(d[0]), "+f"(d[1]), "+f"(d[2]), "+f"(d[3])
        : "r"(a[0]), "r"(a[1]), "r"(a[2]), "r"(a[3]), "r"(b[0]), "r"(b[1]));
}

__device__ __forceinline__ void split_bf16(float v, __nv_bfloat16& h, __nv_bfloat16& l) {
    h = __float2bfloat16(v);
    l = __float2bfloat16(v - __bfloat162float(h));
}

// ---------------- zero per-launch accumulators ----------------
__global__ void zero_kernel() {
    int i = threadIdx.x;
    if (i < NE) { g_cnt[i] = 0; g_sumP[i] = 0.f; }
    if (i == 0) g_zsum = 0.f;
}

// ---------------- router: block-aggregated atomics ----------------
// 1024 threads = 32 warps = 32 tokens per block; 128 blocks.
// Global atomics: 8 cnt + 8 sumP + 1 zsum per BLOCK (vs per token before).
#define RT_TOK 32
__global__ void __launch_bounds__(1024) router_kernel(const float* __restrict__ x,
                                                      const float* __restrict__ rw) {
    __shared__ float s_sumP[NE];
    __shared__ float s_zsum;
    __shared__ int   s_cnt[NE];
    __shared__ int   s_base[NE];
    __shared__ int   s_ebuf[NE][2*RT_TOK];
    __shared__ float s_wbuf[NE][2*RT_TOK];

    int tid  = threadIdx.x;
    int wrp  = tid >> 5;
    int lane = tid & 31;
    int tok  = blockIdx.x * RT_TOK + wrp;

    if (tid < NE) { s_sumP[tid] = 0.f; s_cnt[tid] = 0; }
    if (tid == NE) s_zsum = 0.f;
    __syncthreads();

    const float4* xp = (const float4*)(x + (size_t)tok * DIM);
    float4 xv[4];
#pragma unroll
    for (int i = 0; i < 4; i++) xv[i] = xp[lane * 4 + i];

    float logit[NE];
#pragma unroll
    for (int e = 0; e < NE; e++) {
        const float4* wp = (const float4*)(rw + (size_t)e * DIM);
        float acc = 0.f;
#pragma unroll
        for (int i = 0; i < 4; i++) {
            float4 w4 = wp[lane * 4 + i];
            acc += xv[i].x * w4.x + xv[i].y * w4.y + xv[i].z * w4.z + xv[i].w * w4.w;
        }
#pragma unroll
        for (int o = 16; o > 0; o >>= 1) acc += __shfl_xor_sync(0xffffffffu, acc, o);
        logit[e] = acc;
    }

    if (lane == 0) {
        float m = logit[0];
#pragma unroll
        for (int e = 1; e < NE; e++) m = fmaxf(m, logit[e]);
        float p[NE]; float se = 0.f;
#pragma unroll
        for (int e = 0; e < NE; e++) { p[e] = expf(logit[e] - m); se += p[e]; }
        float inv = 1.f / se;

        int i0 = 0; float v0 = -1.f;
#pragma unroll
        for (int e = 0; e < NE; e++) if (p[e] > v0) { v0 = p[e]; i0 = e; }
        int i1 = -1; float v1 = -1.f;
#pragma unroll
        for (int e = 0; e < NE; e++) if (e != i0 && p[e] > v1) { v1 = p[e]; i1 = e; }

        float s2 = v0 + v1;
        float w0 = v0 / s2, w1 = v1 / s2;

        int p0 = atomicAdd(&s_cnt[i0], 1);
        s_ebuf[i0][p0] = (tok << 1);
        s_wbuf[i0][p0] = w0;
        int p1 = atomicAdd(&s_cnt[i1], 1);
        s_ebuf[i1][p1] = (tok << 1) | 1;
        s_wbuf[i1][p1] = w1;

#pragma unroll
        for (int e = 0; e < NE; e++) atomicAdd(&s_sumP[e], p[e] * inv);
        float lse = m + logf(se);
        atomicAdd(&s_zsum, lse * lse);
    }
    __syncthreads();

    // one global atomic per expert per block to reserve a list range
    if (tid < NE) {
        s_base[tid] = atomicAdd(&g_cnt[tid], s_cnt[tid]);
        atomicAdd(&g_sumP[tid], s_sumP[tid]);
    }
    if (tid == NE) atomicAdd(&g_zsum, s_zsum);
    __syncthreads();

    // cooperative copy-out: warp w handles expert w/4 quarter
    if (wrp < NE * 4) {
        int e = wrp >> 2, q = wrp & 3;
        int c = s_cnt[e], b = s_base[e];
        for (int i = q * 32 + lane; i < c; i += 128) {
            g_list[e * T_TOK + b + i] = s_ebuf[e][i];
            g_wgt [e * T_TOK + b + i] = s_wbuf[e][i];
        }
    }
}

// ---------------- split x into bf16 hi/lo ----------------
__global__ void convert_x_kernel(const float* __restrict__ x) {
    int i = blockIdx.x * blockDim.x + threadIdx.x;
    if (i >= T_TOK * DIM / 4) return;
    float4 v = ((const float4*)x)[i];
    __nv_bfloat16 h0,h1,h2,h3,l0,l1,l2,l3;
    split_bf16(v.x,h0,l0); split_bf16(v.y,h1,l1);
    split_bf16(v.z,h2,l2); split_bf16(v.w,h3,l3);
    ((__nv_bfloat162*)g_xh)[2*i]   = __nv_bfloat162(h0,h1);
    ((__nv_bfloat162*)g_xh)[2*i+1] = __nv_bfloat162(h2,h3);
    ((__nv_bfloat162*)g_xl)[2*i]   = __nv_bfloat162(l0,l1);
    ((__nv_bfloat162*)g_xl)[2*i+1] = __nv_bfloat162(l2,l3);
}

// ---------------- streaming hi/lo split of all weights (no transpose) ----------------
#define WPER (NE*DIM*FDIM/4)   // float4s per tensor = 1048576
__global__ void split_weights_kernel(const float* __restrict__ gw,
                                     const float* __restrict__ uw,
                                     const float* __restrict__ dw) {
    int i = blockIdx.x * blockDim.x + threadIdx.x;
    if (i >= 3 * WPER) return;
    int which = i / WPER, j = i - which * WPER;
    const float* src = (which == 0) ? gw : (which == 1) ? uw : dw;
    __nv_bfloat16* oh = (which == 0) ? g_gh : (which == 1) ? g_uh : g_dh;
    __nv_bfloat16* ol = (which == 0) ? g_gl : (which == 1) ? g_ul : g_dl;
    float4 v = ((const float4*)src)[j];
    __nv_bfloat16 h0,h1,h2,h3,l0,l1,l2,l3;
    split_bf16(v.x,h0,l0); split_bf16(v.y,h1,l1);
    split_bf16(v.z,h2,l2); split_bf16(v.w,h3,l3);
    ((__nv_bfloat162*)oh)[2*(size_t)j]   = __nv_bfloat162(h0,h1);
    ((__nv_bfloat162*)oh)[2*(size_t)j+1] = __nv_bfloat162(h2,h3);
    ((__nv_bfloat162*)ol)[2*(size_t)j]   = __nv_bfloat162(l0,l1);
    ((__nv_bfloat162*)ol)[2*(size_t)j+1] = __nv_bfloat162(l2,l3);
}

// ================= Phase A: gate/up warp-MMA GEMM =================
// Block tile M=128 (gathered pairs) x N=64 (F cols), K chunks of 64 (8 chunks), 3-stage pipeline.
// smem row stride 144B. Per stage: Ah 0, Al 18432, Bgh 36864, Bgl 46080, Buh 55296, Bul 64512; 73728 B.
#define GU_STG  73728
#define GU_SMEM (1024 + 3*GU_STG)

__global__ void __launch_bounds__(256, 1) gateup_mma_kernel() {
    extern __shared__ char smem[];
    uint32_t sb = smem_u32(smem);
    int e = blockIdx.z;
    int cnt = g_cnt[e];
    int row0 = blockIdx.y * 128;
    if (row0 >= cnt) return;
    int col0 = blockIdx.x * 64;
    int tid = threadIdx.x, wid = tid >> 5, lid = tid & 31;
    int wm = wid >> 1, wn = wid & 1;
    int g = lid >> 2, t2 = (lid & 3) * 2;
    int* sTok = (int*)smem;

    for (int i = tid; i < 128; i += 256) {
        int r = row0 + i;
        sTok[i] = (r < cnt) ? g_list[e * T_TOK + r] : -1;
    }
    __syncthreads();

    const __nv_bfloat16* b0 = g_gh + (size_t)e * DIM * FDIM;   // [D][F]
    const __nv_bfloat16* b1 = g_gl + (size_t)e * DIM * FDIM;
    const __nv_bfloat16* b2 = g_uh + (size_t)e * DIM * FDIM;
    const __nv_bfloat16* b3 = g_ul + (size_t)e * DIM * FDIM;

    float accg[2][4][4] = {}, accu[2][4][4] = {};

    auto stage = [&](int chunk) {
        int kt = chunk * 64;
        uint32_t bb = sb + 1024 + (uint32_t)(chunk % 3) * GU_STG;
#pragma unroll
        for (int it = 0; it < 4; it++) {
            int t = tid + it * 256;
            int row = t >> 3, seg = t & 7;
            int entry = sTok[row];
            uint32_t bytes = (entry >= 0) ? 16u : 0u;
            size_t off = (size_t)((entry >= 0) ? (entry >> 1) : 0) * DIM + kt + seg * 8;
            uint32_t d = bb + row * 144 + seg * 16;
            cp16(d,         g_xh + off, bytes);
            cp16(d + 18432, g_xl + off, bytes);
        }
#pragma unroll
        for (int it = 0; it < 8; it++) {
            int t = tid + it * 256;
            int arr = t >> 9, u = t & 511, row = u >> 3, seg = u & 7;
            const __nv_bfloat16* src = (arr == 0) ? b0 : (arr == 1) ? b1 : (arr == 2) ? b2 : b3;
            cp16(bb + 36864 + arr * 9216 + row * 144 + seg * 16,
                 src + (size_t)(kt + row) * FDIM + col0 + seg * 8, 16u);
        }
    };

    uint32_t laneO = (uint32_t)(((lid & 7) + ((lid >> 3) & 1) * 8) * 144 + ((lid >> 4) & 1) * 16);

    stage(0); CP_COMMIT();
    stage(1); CP_COMMIT();
    for (int c = 0; c < 8; c++) {
        if (c + 2 < 8) { stage(c + 2); CP_COMMIT(); CP_WAITG(2); }
        else           { CP_WAITG(0); }
        __syncthreads();
        uint32_t bb = sb + 1024 + (uint32_t)(c % 3) * GU_STG;
        uint32_t aBase = bb + (uint32_t)(wm * 32) * 144 + laneO;
        uint32_t bBase = bb + 36864 + laneO + (uint32_t)(wn * 32) * 2;
#pragma unroll
        for (int kk = 0; kk < 4; kk++) {
            uint32_t ah[2][4], al[2][4];
#pragma unroll
            for (int mt = 0; mt < 2; mt++) {
                uint32_t aa = aBase + mt * (16 * 144) + kk * 32;
                ldsm_x4(ah[mt], aa);
                ldsm_x4(al[mt], aa + 18432);
            }
#pragma unroll
            for (int nt = 0; nt < 2; nt++) {
                uint32_t ba = bBase + kk * (16 * 144) + nt * 32;
                uint32_t bgh[4], bgl[4], buh[4], bul[4];
                ldsm_x4_t(bgh, ba);
                ldsm_x4_t(bgl, ba + 9216);
                ldsm_x4_t(buh, ba + 18432);
                ldsm_x4_t(bul, ba + 27648);
#pragma unroll
                for (int h = 0; h < 2; h++) {
                    int n8 = nt * 2 + h;
#pragma unroll
                    for (int mt = 0; mt < 2; mt++) {
                        mma_bf16(accg[mt][n8], ah[mt], bgh + h * 2);
                        mma_bf16(accg[mt][n8], ah[mt], bgl + h * 2);
                        mma_bf16(accg[mt][n8], al[mt], bgh + h * 2);
                        mma_bf16(accu[mt][n8], ah[mt], buh + h * 2);
                        mma_bf16(accu[mt][n8], ah[mt], bul + h * 2);
                        mma_bf16(accu[mt][n8], al[mt], buh + h * 2);
                    }
                }
            }
        }
        __syncthreads();
    }

    // epilogue: h = silu(gate)*up, split to bf16 hi/lo
#pragma unroll
    for (int mt = 0; mt < 2; mt++) {
        int r0 = wm * 32 + mt * 16 + g;
        int e0 = sTok[r0], e1 = sTok[r0 + 8];
#pragma unroll
        for (int nt = 0; nt < 4; nt++) {
            int colg = col0 + wn * 32 + nt * 8 + t2;
            const float* dg = accg[mt][nt];
            const float* du = accu[mt][nt];
            if (e0 >= 0) {
                float h0 = du[0] * (dg[0] / (1.f + expf(-dg[0])));
                float h1 = du[1] * (dg[1] / (1.f + expf(-dg[1])));
                __nv_bfloat16 h0h, h0l, h1h, h1l;
                split_bf16(h0, h0h, h0l); split_bf16(h1, h1h, h1l);
                *(__nv_bfloat162*)(g_hh + (size_t)e0 * FDIM + colg) = __nv_bfloat162(h0h, h1h);
                *(__nv_bfloat162*)(g_hl + (size_t)e0 * FDIM + colg) = __nv_bfloat162(h0l, h1l);
            }
            if (e1 >= 0) {
                float h0 = du[2] * (dg[2] / (1.f + expf(-dg[2])));
                float h1 = du[3] * (dg[3] / (1.f + expf(-dg[3])));
                __nv_bfloat16 h0h, h0l, h1h, h1l;
                split_bf16(h0, h0h, h0l); split_bf16(h1, h1h, h1l);
                *(__nv_bfloat162*)(g_hh + (size_t)e1 * FDIM + colg) = __nv_bfloat162(h0h, h1h);
                *(__nv_bfloat162*)(g_hl + (size_t)e1 * FDIM + colg) = __nv_bfloat162(h0l, h1l);
            }
        }
    }
}

// ================= Phase B: down warp-MMA GEMM =================
// Block tile M=128 x N=64 (D cols), K=1024 in 16 chunks of 64, 4-stage pipeline.
// Per stage: Ah 0, Al 18432, Bh 36864, Bl 46080; 55296 B.
#define DN_STG  55296
#define DN_SMEM (1024 + 4*DN_STG)

__global__ void __launch_bounds__(256, 1) down_mma_kernel() {
    extern __shared__ char smem[];
    uint32_t sb = smem_u32(smem);
    int e = blockIdx.z;
    int cnt = g_cnt[e];
    int row0 = blockIdx.y * 128;
    if (row0 >= cnt) return;
    int col0 = blockIdx.x * 64;
    int tid = threadIdx.x, wid = tid >> 5, lid = tid & 31;
    int wm = wid >> 1, wn = wid & 1;
    int g = lid >> 2, t2 = (lid & 3) * 2;
    int*   sTok = (int*)smem;
    float* sW   = (float*)(smem + 512);

    for (int i = tid; i < 128; i += 256) {
        int r = row0 + i;
        sTok[i] = (r < cnt) ? g_list[e * T_TOK + r] : -1;
        sW[i]   = (r < cnt) ? g_wgt [e * T_TOK + r] : 0.f;
    }
    __syncthreads();

    const __nv_bfloat16* dh = g_dh + (size_t)e * FDIM * DIM;   // [F][D]
    const __nv_bfloat16* dl = g_dl + (size_t)e * FDIM * DIM;

    float acc[2][4][4] = {};

    auto stage = [&](int chunk) {
        int kt = chunk * 64;
        uint32_t bb = sb + 1024 + (uint32_t)(chunk & 3) * DN_STG;
#pragma unroll
        for (int it = 0; it < 8; it++) {
            int t = tid + it * 256;
            int arr = t >> 10, u = t & 1023, row = u >> 3, seg = u & 7;
            int entry = sTok[row];
            uint32_t bytes = (entry >= 0) ? 16u : 0u;
            const __nv_bfloat16* src = (arr ? g_hl : g_hh)
                + (size_t)((entry >= 0) ? entry : 0) * FDIM + kt + seg * 8;
            cp16(bb + arr * 18432 + row * 144 + seg * 16, src, bytes);
        }
#pragma unroll
        for (int it = 0; it < 4; it++) {
            int t = tid + it * 256;
            int arr = t >> 9, u = t & 511, row = u >> 3, seg = u & 7;
            const __nv_bfloat16* src = (arr ? dl : dh)
                + (size_t)(kt + row) * DIM + col0 + seg * 8;
            cp16(bb + 36864 + arr * 9216 + row * 144 + seg * 16, src, 16u);
        }
    };

    uint32_t laneO = (uint32_t)(((lid & 7) + ((lid >> 3) & 1) * 8) * 144 + ((lid >> 4) & 1) * 16);

    stage(0); CP_COMMIT();
    stage(1); CP_COMMIT();
    stage(2); CP_COMMIT();
    for (int c = 0; c < 16; c++) {
        if (c + 3 < 16) { stage(c + 3); CP_COMMIT(); CP_WAITG(3); }
        else            { CP_WAITG(0); }
        __syncthreads();
        uint32_t bb = sb + 1024 + (uint32_t)(c & 3) * DN_STG;
        uint32_t aBase = bb + (uint32_t)(wm * 32) * 144 + laneO;
        uint32_t bBase = bb + 36864 + laneO + (uint32_t)(wn * 32) * 2;
#pragma unroll
        for (int kk = 0; kk < 4; kk++) {
            uint32_t ah[2][4], al[2][4];
#pragma unroll
            for (int mt = 0; mt < 2; mt++) {
                uint32_t aa = aBase + mt * (16 * 144) + kk * 32;
                ldsm_x4(ah[mt], aa);
                ldsm_x4(al[mt], aa + 18432);
            }
#pragma unroll
            for (int nt = 0; nt < 2; nt++) {
                uint32_t ba = bBase + kk * (16 * 144) + nt * 32;
                uint32_t bh[4], bl[4];
                ldsm_x4_t(bh, ba);
                ldsm_x4_t(bl, ba + 9216);
#pragma unroll
                for (int h = 0; h < 2; h++) {
                    int n8 = nt * 2 + h;
#pragma unroll
                    for (int mt = 0; mt < 2; mt++) {
                        mma_bf16(acc[mt][n8], ah[mt], bh + h * 2);
                        mma_bf16(acc[mt][n8], ah[mt], bl + h * 2);
                        mma_bf16(acc[mt][n8], al[mt], bh + h * 2);
                    }
                }
            }
        }
        __syncthreads();
    }

    // epilogue: scale by combine weight, write per-pair slot
#pragma unroll
    for (int mt = 0; mt < 2; mt++) {
        int r0 = wm * 32 + mt * 16 + g;
        int e0 = sTok[r0], e1 = sTok[r0 + 8];
        float w0 = sW[r0], w1 = sW[r0 + 8];
#pragma unroll
        for (int nt = 0; nt < 4; nt++) {
            int cg = col0 + wn * 32 + nt * 8 + t2;
            const float* d = acc[mt][nt];
            if (e0 >= 0) {
                float2 o = make_float2(w0 * d[0], w0 * d[1]);
                *(float2*)(g_pout + (size_t)e0 * DIM + cg) = o;
            }
            if (e1 >= 0) {
                float2 o = make_float2(w1 * d[2], w1 * d[3]);
                *(float2*)(g_pout + (size_t)e1 * DIM + cg) = o;
            }
        }
    }
}

// ---------------- combine the two pair slots per token ----------------
__global__ void combine_kernel(float* __restrict__ out) {
    int i = blockIdx.x * blockDim.x + threadIdx.x;
    const int N4 = T_TOK * DIM / 4;
    const int D4 = DIM / 4;
    if (i >= N4) return;
    int t = i / D4, c = i % D4;
    const float4* p = (const float4*)g_pout;
    float4 a = p[(size_t)(2 * t) * D4 + c];
    float4 b = p[(size_t)(2 * t + 1) * D4 + c];
    ((float4*)out)[i] = make_float4(a.x + b.x, a.y + b.y, a.z + b.z, a.w + b.w);
}

// ---------------- aux loss ----------------
__global__ void finalize_kernel(float* __restrict__ out, int out_size) {
    float lb = 0.f;
#pragma unroll
    for (int e = 0; e < NE; e++)
        lb += ((float)g_cnt[e] / (float)NPAIR) * (g_sumP[e] / (float)T_TOK);
    float aux = 0.01f * (float)NE * lb + 0.001f * (g_zsum / (float)T_TOK);
    out[out_size - 1] = aux;
}

// ---------------- launch ----------------
extern "C" void kernel_launch(void* const* d_in, const int* in_sizes, int n_in,
                              void* d_out, int out_size) {
    const float* x  = (const float*)d_in[0];
    const float* rw = (const float*)d_in[1];
    const float* gw = (const float*)d_in[2];
    const float* uw = (const float*)d_in[3];
    const float* dw = (const float*)d_in[4];
    float* out = (float*)d_out;

    cudaFuncSetAttribute(gateup_mma_kernel, cudaFuncAttributeMaxDynamicSharedMemorySize, GU_SMEM);
    cudaFuncSetAttribute(down_mma_kernel,   cudaFuncAttributeMaxDynamicSharedMemorySize, DN_SMEM);

    zero_kernel<<<1, 32>>>();
    convert_x_kernel<<<(T_TOK * DIM / 4 + 255) / 256, 256>>>(x);
    split_weights_kernel<<<(3 * WPER + 255) / 256, 256>>>(gw, uw, dw);
    router_kernel<<<T_TOK / RT_TOK, 1024>>>(x, rw);
    gateup_mma_kernel<<<dim3(FDIM / 64, T_TOK / 128, NE), 256, GU_SMEM>>>();
    down_mma_kernel<<<dim3(DIM / 64, T_TOK / 128, NE), 256, DN_SMEM>>>();
    combine_kernel<<<(T_TOK * DIM / 4 + 255) / 256, 256>>>(out);
    finalize_kernel<<<1, 1>>>(out, out_size);
}

// round 10
// speedup vs baseline: 2.2080x; 1.1181x over previous
#include <cuda_runtime.h>
#include <cuda_bf16.h>
#include <math.h>
#include <stdint.h>

// Problem constants (fixed shapes)
#define T_TOK 4096
#define DIM   512
#define FDIM  1024
#define NE    8
#define TOPK  2
#define NPAIR (T_TOK*TOPK)

// ---------------- device scratch (static; no runtime allocation) ----------------
__device__ int   g_cnt[NE];
__device__ int   g_list[NE*T_TOK];   // packed (token<<1)|k
__device__ float g_wgt [NE*T_TOK];
__device__ float g_sumP[NE];
__device__ float g_zsum;

// bf16 hi/lo splits (NATURAL layouts — no transpose)
__device__ __nv_bfloat16 g_xh[(size_t)T_TOK*DIM];
__device__ __nv_bfloat16 g_xl[(size_t)T_TOK*DIM];
__device__ __nv_bfloat16 g_gh[(size_t)NE*DIM*FDIM];  // gate [E][D][F]
__device__ __nv_bfloat16 g_gl[(size_t)NE*DIM*FDIM];
__device__ __nv_bfloat16 g_uh[(size_t)NE*DIM*FDIM];  // up   [E][D][F]
__device__ __nv_bfloat16 g_ul[(size_t)NE*DIM*FDIM];
__device__ __nv_bfloat16 g_dh[(size_t)NE*FDIM*DIM];  // down [E][F][D]
__device__ __nv_bfloat16 g_dl[(size_t)NE*FDIM*DIM];
__device__ __nv_bfloat16 g_hh[(size_t)NPAIR*FDIM];   // hidden hi
__device__ __nv_bfloat16 g_hl[(size_t)NPAIR*FDIM];   // hidden lo
__device__ float g_pout[(size_t)NPAIR*DIM];

// ================= PTX helpers (family-portable: sm_80+) =================
__device__ __forceinline__ uint32_t smem_u32(const void* p) {
    uint32_t a;
    asm("{ .reg .u64 t; cvta.to.shared.u64 t, %1; cvt.u32.u64 %0, t; }" : "=r"(a) : "l"(p));
    return a;
}
__device__ __forceinline__ void cp16(uint32_t dst, const void* src, uint32_t bytes) {
    asm volatile("cp.async.cg.shared.global [%0], [%1], 16, %2;"
                 :: "r"(dst), "l"(src), "r"(bytes) : "memory");
}
#define CP_COMMIT() asm volatile("cp.async.commit_group;" ::: "memory")
#define CP_WAITG(n) asm volatile("cp.async.wait_group %0;" :: "n"(n) : "memory")

__device__ __forceinline__ void ldsm_x4(uint32_t* r, uint32_t addr) {
    asm volatile("ldmatrix.sync.aligned.m8n8.x4.shared.b16 {%0,%1,%2,%3}, [%4];"
        : "=r"(r[0]), "=r"(r[1]), "=r"(r[2]), "=r"(r[3]) : "r"(addr));
}
__device__ __forceinline__ void ldsm_x4_t(uint32_t* r, uint32_t addr) {
    asm volatile("ldmatrix.sync.aligned.m8n8.x4.trans.shared.b16 {%0,%1,%2,%3}, [%4];"
        : "=r"(r[0]), "=r"(r[1]), "=r"(r[2]), "=r"(r[3]) : "r"(addr));
}
__device__ __forceinline__ void mma_bf16(float* d, const uint32_t* a, const uint32_t* b) {
    asm volatile("mma.sync.aligned.m16n8k16.row.col.f32.bf16.bf16.f32 "
        "{%0,%1,%2,%3}, {%4,%5,%6,%7}, {%8,%9}, {%0,%1,%2,%3};"
        : "+f"(d[0]), "+f"(d[1]), "+f"(d[2]), "+f"(d[3])
        : "r"(a[0]), "r"(a[1]), "r"(a[2]), "r"(a[3]), "r"(b[0]), "r"(b[1]));
}

__device__ __forceinline__ void split_bf16(float v, __nv_bfloat16& h, __nv_bfloat16& l) {
    h = __float2bfloat16(v);
    l = __float2bfloat16(v - __bfloat162float(h));
}

// ---------------- zero per-launch accumulators ----------------
__global__ void zero_kernel() {
    int i = threadIdx.x;
    if (i < NE) { g_cnt[i] = 0; g_sumP[i] = 0.f; }
    if (i == 0) g_zsum = 0.f;
}

// ---------------- router: lane-partitioned logits + block-aggregated atomics ----------------
// 512 threads = 16 warps = 16 tokens per block; 256 blocks.
// Each lane computes partial for expert (lane>>2) over D-quarter (lane&3): 2 shfl reduce.
#define RT_TOK 16
__global__ void __launch_bounds__(512) router_kernel(const float* __restrict__ x,
                                                     const float* __restrict__ rw) {
    __shared__ float s_sumP[NE];
    __shared__ float s_zsum;
    __shared__ int   s_cnt[NE];
    __shared__ int   s_base[NE];
    __shared__ int   s_ebuf[NE][2*RT_TOK];
    __shared__ float s_wbuf[NE][2*RT_TOK];

    int tid  = threadIdx.x;
    int wrp  = tid >> 5;
    int lane = tid & 31;
    int tok  = blockIdx.x * RT_TOK + wrp;

    if (tid < NE) { s_sumP[tid] = 0.f; s_cnt[tid] = 0; }
    if (tid == NE) s_zsum = 0.f;
    __syncthreads();

    int eL = lane >> 2;    // expert this lane accumulates
    int qL = lane & 3;     // D-quarter
    const float4* xq = (const float4*)(x  + (size_t)tok * DIM) + qL * 32;
    const float4* wq = (const float4*)(rw + (size_t)eL  * DIM) + qL * 32;
    float acc = 0.f;
#pragma unroll 8
    for (int i = 0; i < 32; i++) {
        float4 a = xq[i], b = wq[i];
        acc += a.x*b.x + a.y*b.y + a.z*b.z + a.w*b.w;
    }
    acc += __shfl_xor_sync(0xffffffffu, acc, 1);
    acc += __shfl_xor_sync(0xffffffffu, acc, 2);

    float logit[NE];
#pragma unroll
    for (int e = 0; e < NE; e++) logit[e] = __shfl_sync(0xffffffffu, acc, e * 4);

    if (lane == 0) {
        float m = logit[0];
#pragma unroll
        for (int e = 1; e < NE; e++) m = fmaxf(m, logit[e]);
        float p[NE]; float se = 0.f;
#pragma unroll
        for (int e = 0; e < NE; e++) { p[e] = expf(logit[e] - m); se += p[e]; }
        float inv = 1.f / se;

        int i0 = 0; float v0 = -1.f;
#pragma unroll
        for (int e = 0; e < NE; e++) if (p[e] > v0) { v0 = p[e]; i0 = e; }
        int i1 = -1; float v1 = -1.f;
#pragma unroll
        for (int e = 0; e < NE; e++) if (e != i0 && p[e] > v1) { v1 = p[e]; i1 = e; }

        float s2 = v0 + v1;
        float w0 = v0 / s2, w1 = v1 / s2;

        int p0 = atomicAdd(&s_cnt[i0], 1);
        s_ebuf[i0][p0] = (tok << 1);
        s_wbuf[i0][p0] = w0;
        int p1 = atomicAdd(&s_cnt[i1], 1);
        s_ebuf[i1][p1] = (tok << 1) | 1;
        s_wbuf[i1][p1] = w1;

#pragma unroll
        for (int e = 0; e < NE; e++) atomicAdd(&s_sumP[e], p[e] * inv);
        float lse = m + logf(se);
        atomicAdd(&s_zsum, lse * lse);
    }
    __syncthreads();

    if (tid < NE) {
        s_base[tid] = atomicAdd(&g_cnt[tid], s_cnt[tid]);
        atomicAdd(&g_sumP[tid], s_sumP[tid]);
    }
    if (tid == NE) atomicAdd(&g_zsum, s_zsum);
    __syncthreads();

    // copy-out: 16 warps, 2 warps per expert
    {
        int e = wrp >> 1, part = wrp & 1;
        int c = s_cnt[e], b = s_base[e];
        for (int i = part * 32 + lane; i < c; i += 64) {
            g_list[e * T_TOK + b + i] = s_ebuf[e][i];
            g_wgt [e * T_TOK + b + i] = s_wbuf[e][i];
        }
    }
}

// ---------------- split x into bf16 hi/lo ----------------
__global__ void convert_x_kernel(const float* __restrict__ x) {
    int i = blockIdx.x * blockDim.x + threadIdx.x;
    if (i >= T_TOK * DIM / 4) return;
    float4 v = ((const float4*)x)[i];
    __nv_bfloat16 h0,h1,h2,h3,l0,l1,l2,l3;
    split_bf16(v.x,h0,l0); split_bf16(v.y,h1,l1);
    split_bf16(v.z,h2,l2); split_bf16(v.w,h3,l3);
    ((__nv_bfloat162*)g_xh)[2*i]   = __nv_bfloat162(h0,h1);
    ((__nv_bfloat162*)g_xh)[2*i+1] = __nv_bfloat162(h2,h3);
    ((__nv_bfloat162*)g_xl)[2*i]   = __nv_bfloat162(l0,l1);
    ((__nv_bfloat162*)g_xl)[2*i+1] = __nv_bfloat162(l2,l3);
}

// ---------------- streaming hi/lo split of all weights ----------------
#define WPER (NE*DIM*FDIM/4)   // float4s per tensor = 1048576
__global__ void split_weights_kernel(const float* __restrict__ gw,
                                     const float* __restrict__ uw,
                                     const float* __restrict__ dw) {
    int i = blockIdx.x * blockDim.x + threadIdx.x;
    if (i >= 3 * WPER) return;
    int which = i / WPER, j = i - which * WPER;
    const float* src = (which == 0) ? gw : (which == 1) ? uw : dw;
    __nv_bfloat16* oh = (which == 0) ? g_gh : (which == 1) ? g_uh : g_dh;
    __nv_bfloat16* ol = (which == 0) ? g_gl : (which == 1) ? g_ul : g_dl;
    float4 v = ((const float4*)src)[j];
    __nv_bfloat16 h0,h1,h2,h3,l0,l1,l2,l3;
    split_bf16(v.x,h0,l0); split_bf16(v.y,h1,l1);
    split_bf16(v.z,h2,l2); split_bf16(v.w,h3,l3);
    ((__nv_bfloat162*)oh)[2*(size_t)j]   = __nv_bfloat162(h0,h1);
    ((__nv_bfloat162*)oh)[2*(size_t)j+1] = __nv_bfloat162(h2,h3);
    ((__nv_bfloat162*)ol)[2*(size_t)j]   = __nv_bfloat162(l0,l1);
    ((__nv_bfloat162*)ol)[2*(size_t)j+1] = __nv_bfloat162(l2,l3);
}

// ================= Phase A: gate/up warp-MMA GEMM =================
// Block tile M=64 x N=64, K chunks of 64 (8 chunks), 2-stage pipeline.
// smem row stride 144B. Per stage: Ah 0, Al 9216, then B at 18432: Bgh, Bgl, Buh, Bul (9216 each).
// Stage = 55296 B; 2 stages + 1KB hdr = 111616 -> 2 blocks/SM.
#define GU_STG  55296
#define GU_SMEM (1024 + 2*GU_STG)

__global__ void __launch_bounds__(256, 2) gateup_mma_kernel() {
    extern __shared__ char smem[];
    uint32_t sb = smem_u32(smem);
    int e = blockIdx.z;
    int cnt = g_cnt[e];
    int row0 = blockIdx.y * 64;
    if (row0 >= cnt) return;
    int col0 = blockIdx.x * 64;
    int tid = threadIdx.x, wid = tid >> 5, lid = tid & 31;
    int wm = wid >> 2, wn = wid & 3;          // 2 x 4 warp grid: M32 x N16
    int g = lid >> 2, t2 = (lid & 3) * 2;
    int* sTok = (int*)smem;

    for (int i = tid; i < 64; i += 256) {
        int r = row0 + i;
        sTok[i] = (r < cnt) ? g_list[e * T_TOK + r] : -1;
    }
    __syncthreads();

    const __nv_bfloat16* b0 = g_gh + (size_t)e * DIM * FDIM;   // [D][F]
    const __nv_bfloat16* b1 = g_gl + (size_t)e * DIM * FDIM;
    const __nv_bfloat16* b2 = g_uh + (size_t)e * DIM * FDIM;
    const __nv_bfloat16* b3 = g_ul + (size_t)e * DIM * FDIM;

    float accg[2][2][4] = {}, accu[2][2][4] = {};

    auto stage = [&](int chunk) {
        int kt = chunk * 64;
        uint32_t bb = sb + 1024 + (uint32_t)(chunk & 1) * GU_STG;
        // A hi/lo gathered: 2 arrays x 64 rows x 8 segs = 1024 cp16
#pragma unroll
        for (int it = 0; it < 4; it++) {
            int t = tid + it * 256;
            int arr = t >> 9, u = t & 511, row = u >> 3, seg = u & 7;
            int entry = sTok[row];
            uint32_t bytes = (entry >= 0) ? 16u : 0u;
            const __nv_bfloat16* src = (arr ? g_xl : g_xh)
                + (size_t)((entry >= 0) ? (entry >> 1) : 0) * DIM + kt + seg * 8;
            cp16(bb + arr * 9216 + row * 144 + seg * 16, src, bytes);
        }
        // B natural [64 K][64 N]: 4 arrays x 512 = 2048 cp16
#pragma unroll
        for (int it = 0; it < 8; it++) {
            int t = tid + it * 256;
            int arr = t >> 9, u = t & 511, row = u >> 3, seg = u & 7;
            const __nv_bfloat16* src = (arr == 0) ? b0 : (arr == 1) ? b1 : (arr == 2) ? b2 : b3;
            cp16(bb + 18432 + arr * 9216 + row * 144 + seg * 16,
                 src + (size_t)(kt + row) * FDIM + col0 + seg * 8, 16u);
        }
    };

    uint32_t laneO = (uint32_t)(((lid & 7) + ((lid >> 3) & 1) * 8) * 144 + ((lid >> 4) & 1) * 16);

    stage(0); CP_COMMIT();
    for (int c = 0; c < 8; c++) {
        if (c + 1 < 8) { stage(c + 1); CP_COMMIT(); CP_WAITG(1); }
        else           { CP_WAITG(0); }
        __syncthreads();
        uint32_t bb = sb + 1024 + (uint32_t)(c & 1) * GU_STG;
        uint32_t aBase = bb + (uint32_t)(wm * 32) * 144 + laneO;
        uint32_t bBase = bb + 18432 + laneO + (uint32_t)(wn * 16) * 2;
#pragma unroll
        for (int kk = 0; kk < 4; kk++) {
            uint32_t ah[2][4], al[2][4];
#pragma unroll
            for (int mt = 0; mt < 2; mt++) {
                uint32_t aa = aBase + mt * (16 * 144) + kk * 32;
                ldsm_x4(ah[mt], aa);
                ldsm_x4(al[mt], aa + 9216);
            }
            uint32_t ba = bBase + kk * (16 * 144);
            uint32_t bgh[4], bgl[4], buh[4], bul[4];
            ldsm_x4_t(bgh, ba);
            ldsm_x4_t(bgl, ba + 9216);
            ldsm_x4_t(buh, ba + 18432);
            ldsm_x4_t(bul, ba + 27648);
#pragma unroll
            for (int h = 0; h < 2; h++) {
#pragma unroll
                for (int mt = 0; mt < 2; mt++) {
                    mma_bf16(accg[mt][h], ah[mt], bgh + h * 2);
                    mma_bf16(accg[mt][h], ah[mt], bgl + h * 2);
                    mma_bf16(accg[mt][h], al[mt], bgh + h * 2);
                    mma_bf16(accu[mt][h], ah[mt], buh + h * 2);
                    mma_bf16(accu[mt][h], ah[mt], bul + h * 2);
                    mma_bf16(accu[mt][h], al[mt], buh + h * 2);
                }
            }
        }
        __syncthreads();
    }

    // epilogue: h = silu(gate)*up, split to bf16 hi/lo
#pragma unroll
    for (int mt = 0; mt < 2; mt++) {
        int r0 = wm * 32 + mt * 16 + g;
        int e0 = sTok[r0], e1 = sTok[r0 + 8];
#pragma unroll
        for (int h = 0; h < 2; h++) {
            int colg = col0 + wn * 16 + h * 8 + t2;
            const float* dg = accg[mt][h];
            const float* du = accu[mt][h];
            if (e0 >= 0) {
                float h0 = du[0] * (dg[0] / (1.f + expf(-dg[0])));
                float h1 = du[1] * (dg[1] / (1.f + expf(-dg[1])));
                __nv_bfloat16 h0h, h0l, h1h, h1l;
                split_bf16(h0, h0h, h0l); split_bf16(h1, h1h, h1l);
                *(__nv_bfloat162*)(g_hh + (size_t)e0 * FDIM + colg) = __nv_bfloat162(h0h, h1h);
                *(__nv_bfloat162*)(g_hl + (size_t)e0 * FDIM + colg) = __nv_bfloat162(h0l, h1l);
            }
            if (e1 >= 0) {
                float h0 = du[2] * (dg[2] / (1.f + expf(-dg[2])));
                float h1 = du[3] * (dg[3] / (1.f + expf(-dg[3])));
                __nv_bfloat16 h0h, h0l, h1h, h1l;
                split_bf16(h0, h0h, h0l); split_bf16(h1, h1h, h1l);
                *(__nv_bfloat162*)(g_hh + (size_t)e1 * FDIM + colg) = __nv_bfloat162(h0h, h1h);
                *(__nv_bfloat162*)(g_hl + (size_t)e1 * FDIM + colg) = __nv_bfloat162(h0l, h1l);
            }
        }
    }
}

// ================= Phase B: down warp-MMA GEMM =================
// Block tile M=64 x N=64, K=1024 in 16 chunks of 64, 2-stage pipeline.
// Per stage: Ah 0, Al 9216, Bh 18432, Bl 27648; 36864 B. 2 stages + 1KB = 74752 -> 3 blocks/SM.
#define DN_STG  36864
#define DN_SMEM (1024 + 2*DN_STG)

__global__ void __launch_bounds__(256, 2) down_mma_kernel() {
    extern __shared__ char smem[];
    uint32_t sb = smem_u32(smem);
    int e = blockIdx.z;
    int cnt = g_cnt[e];
    int row0 = blockIdx.y * 64;
    if (row0 >= cnt) return;
    int col0 = blockIdx.x * 64;
    int tid = threadIdx.x, wid = tid >> 5, lid = tid & 31;
    int wm = wid >> 2, wn = wid & 3;
    int g = lid >> 2, t2 = (lid & 3) * 2;
    int*   sTok = (int*)smem;
    float* sW   = (float*)(smem + 256);

    for (int i = tid; i < 64; i += 256) {
        int r = row0 + i;
        sTok[i] = (r < cnt) ? g_list[e * T_TOK + r] : -1;
        sW[i]   = (r < cnt) ? g_wgt [e * T_TOK + r] : 0.f;
    }
    __syncthreads();

    const __nv_bfloat16* dh = g_dh + (size_t)e * FDIM * DIM;   // [F][D]
    const __nv_bfloat16* dl = g_dl + (size_t)e * FDIM * DIM;

    float acc[2][2][4] = {};

    auto stage = [&](int chunk) {
        int kt = chunk * 64;
        uint32_t bb = sb + 1024 + (uint32_t)(chunk & 1) * DN_STG;
        // A hidden hi/lo gathered: 1024 cp16
#pragma unroll
        for (int it = 0; it < 4; it++) {
            int t = tid + it * 256;
            int arr = t >> 9, u = t & 511, row = u >> 3, seg = u & 7;
            int entry = sTok[row];
            uint32_t bytes = (entry >= 0) ? 16u : 0u;
            const __nv_bfloat16* src = (arr ? g_hl : g_hh)
                + (size_t)((entry >= 0) ? entry : 0) * FDIM + kt + seg * 8;
            cp16(bb + arr * 9216 + row * 144 + seg * 16, src, bytes);
        }
        // B natural [64 K][64 N]: 1024 cp16
#pragma unroll
        for (int it = 0; it < 4; it++) {
            int t = tid + it * 256;
            int arr = t >> 9, u = t & 511, row = u >> 3, seg = u & 7;
            const __nv_bfloat16* src = (arr ? dl : dh)
                + (size_t)(kt + row) * DIM + col0 + seg * 8;
            cp16(bb + 18432 + arr * 9216 + row * 144 + seg * 16, src, 16u);
        }
    };

    uint32_t laneO = (uint32_t)(((lid & 7) + ((lid >> 3) & 1) * 8) * 144 + ((lid >> 4) & 1) * 16);

    stage(0); CP_COMMIT();
    for (int c = 0; c < 16; c++) {
        if (c + 1 < 16) { stage(c + 1); CP_COMMIT(); CP_WAITG(1); }
        else            { CP_WAITG(0); }
        __syncthreads();
        uint32_t bb = sb + 1024 + (uint32_t)(c & 1) * DN_STG;
        uint32_t aBase = bb + (uint32_t)(wm * 32) * 144 + laneO;
        uint32_t bBase = bb + 18432 + laneO + (uint32_t)(wn * 16) * 2;
#pragma unroll
        for (int kk = 0; kk < 4; kk++) {
            uint32_t ah[2][4], al[2][4];
#pragma unroll
            for (int mt = 0; mt < 2; mt++) {
                uint32_t aa = aBase + mt * (16 * 144) + kk * 32;
                ldsm_x4(ah[mt], aa);
                ldsm_x4(al[mt], aa + 9216);
            }
            uint32_t ba = bBase + kk * (16 * 144);
            uint32_t bh[4], bl[4];
            ldsm_x4_t(bh, ba);
            ldsm_x4_t(bl, ba + 9216);
#pragma unroll
            for (int h = 0; h < 2; h++) {
#pragma unroll
                for (int mt = 0; mt < 2; mt++) {
                    mma_bf16(acc[mt][h], ah[mt], bh + h * 2);
                    mma_bf16(acc[mt][h], ah[mt], bl + h * 2);
                    mma_bf16(acc[mt][h], al[mt], bh + h * 2);
                }
            }
        }
        __syncthreads();
    }

    // epilogue: scale by combine weight, write per-pair slot
#pragma unroll
    for (int mt = 0; mt < 2; mt++) {
        int r0 = wm * 32 + mt * 16 + g;
        int e0 = sTok[r0], e1 = sTok[r0 + 8];
        float w0 = sW[r0], w1 = sW[r0 + 8];
#pragma unroll
        for (int h = 0; h < 2; h++) {
            int cg = col0 + wn * 16 + h * 8 + t2;
            const float* d = acc[mt][h];
            if (e0 >= 0) {
                float2 o = make_float2(w0 * d[0], w0 * d[1]);
                *(float2*)(g_pout + (size_t)e0 * DIM + cg) = o;
            }
            if (e1 >= 0) {
                float2 o = make_float2(w1 * d[2], w1 * d[3]);
                *(float2*)(g_pout + (size_t)e1 * DIM + cg) = o;
            }
        }
    }
}

// ---------------- combine the two pair slots per token ----------------
__global__ void combine_kernel(float* __restrict__ out) {
    int i = blockIdx.x * blockDim.x + threadIdx.x;
    const int N4 = T_TOK * DIM / 4;
    const int D4 = DIM / 4;
    if (i >= N4) return;
    int t = i / D4, c = i % D4;
    const float4* p = (const float4*)g_pout;
    float4 a = p[(size_t)(2 * t) * D4 + c];
    float4 b = p[(size_t)(2 * t + 1) * D4 + c];
    ((float4*)out)[i] = make_float4(a.x + b.x, a.y + b.y, a.z + b.z, a.w + b.w);
}

// ---------------- aux loss ----------------
__global__ void finalize_kernel(float* __restrict__ out, int out_size) {
    float lb = 0.f;
#pragma unroll
    for (int e = 0; e < NE; e++)
        lb += ((float)g_cnt[e] / (float)NPAIR) * (g_sumP[e] / (float)T_TOK);
    float aux = 0.01f * (float)NE * lb + 0.001f * (g_zsum / (float)T_TOK);
    out[out_size - 1] = aux;
}

// ---------------- launch ----------------
extern "C" void kernel_launch(void* const* d_in, const int* in_sizes, int n_in,
                              void* d_out, int out_size) {
    const float* x  = (const float*)d_in[0];
    const float* rw = (const float*)d_in[1];
    const float* gw = (const float*)d_in[2];
    const float* uw = (const float*)d_in[3];
    const float* dw = (const float*)d_in[4];
    float* out = (float*)d_out;

    cudaFuncSetAttribute(gateup_mma_kernel, cudaFuncAttributeMaxDynamicSharedMemorySize, GU_SMEM);
    cudaFuncSetAttribute(down_mma_kernel,   cudaFuncAttributeMaxDynamicSharedMemorySize, DN_SMEM);

    zero_kernel<<<1, 32>>>();
    convert_x_kernel<<<(T_TOK * DIM / 4 + 255) / 256, 256>>>(x);
    split_weights_kernel<<<(3 * WPER + 255) / 256, 256>>>(gw, uw, dw);
    router_kernel<<<T_TOK / RT_TOK, 512>>>(x, rw);
    gateup_mma_kernel<<<dim3(FDIM / 64, T_TOK / 64, NE), 256, GU_SMEM>>>();
    down_mma_kernel<<<dim3(DIM / 64, T_TOK / 64, NE), 256, DN_SMEM>>>();
    combine_kernel<<<(T_TOK * DIM / 4 + 255) / 256, 256>>>(out);
    finalize_kernel<<<1, 1>>>(out, out_size);
}

// round 11
// speedup vs baseline: 2.3514x; 1.0649x over previous
#include <cuda_runtime.h>
#include <cuda_bf16.h>
#include <math.h>
#include <stdint.h>

// Problem constants (fixed shapes)
#define T_TOK 4096
#define DIM   512
#define FDIM  1024
#define NE    8
#define TOPK  2
#define NPAIR (T_TOK*TOPK)

// ---------------- device scratch (static; no runtime allocation) ----------------
__device__ int   g_cnt[NE];
__device__ int   g_list[NE*T_TOK];   // packed (token<<1)|k
__device__ float g_wgt [NE*T_TOK];
__device__ float g_sumP[NE];
__device__ float g_zsum;

// bf16 hi/lo splits (NATURAL layouts — no transpose)
__device__ __nv_bfloat16 g_xh[(size_t)T_TOK*DIM];
__device__ __nv_bfloat16 g_xl[(size_t)T_TOK*DIM];
__device__ __nv_bfloat16 g_gh[(size_t)NE*DIM*FDIM];  // gate [E][D][F]
__device__ __nv_bfloat16 g_gl[(size_t)NE*DIM*FDIM];
__device__ __nv_bfloat16 g_uh[(size_t)NE*DIM*FDIM];  // up   [E][D][F]
__device__ __nv_bfloat16 g_ul[(size_t)NE*DIM*FDIM];
__device__ __nv_bfloat16 g_dh[(size_t)NE*FDIM*DIM];  // down [E][F][D]
__device__ __nv_bfloat16 g_dl[(size_t)NE*FDIM*DIM];
__device__ __nv_bfloat16 g_hh[(size_t)NPAIR*FDIM];   // hidden hi
__device__ __nv_bfloat16 g_hl[(size_t)NPAIR*FDIM];   // hidden lo
__device__ float g_pout[(size_t)NPAIR*DIM];

// ================= PTX helpers (family-portable: sm_80+) =================
__device__ __forceinline__ uint32_t smem_u32(const void* p) {
    uint32_t a;
    asm("{ .reg .u64 t; cvta.to.shared.u64 t, %1; cvt.u32.u64 %0, t; }" : "=r"(a) : "l"(p));
    return a;
}
__device__ __forceinline__ void cp16(uint32_t dst, const void* src, uint32_t bytes) {
    asm volatile("cp.async.cg.shared.global [%0], [%1], 16, %2;"
                 :: "r"(dst), "l"(src), "r"(bytes) : "memory");
}
#define CP_COMMIT() asm volatile("cp.async.commit_group;" ::: "memory")
#define CP_WAITG(n) asm volatile("cp.async.wait_group %0;" :: "n"(n) : "memory")

__device__ __forceinline__ void ldsm_x4(uint32_t* r, uint32_t addr) {
    asm volatile("ldmatrix.sync.aligned.m8n8.x4.shared.b16 {%0,%1,%2,%3}, [%4];"
        : "=r"(r[0]), "=r"(r[1]), "=r"(r[2]), "=r"(r[3]) : "r"(addr));
}
__device__ __forceinline__ void ldsm_x4_t(uint32_t* r, uint32_t addr) {
    asm volatile("ldmatrix.sync.aligned.m8n8.x4.trans.shared.b16 {%0,%1,%2,%3}, [%4];"
        : "=r"(r[0]), "=r"(r[1]), "=r"(r[2]), "=r"(r[3]) : "r"(addr));
}
__device__ __forceinline__ void mma_bf16(float* d, const uint32_t* a, const uint32_t* b) {
    asm volatile("mma.sync.aligned.m16n8k16.row.col.f32.bf16.bf16.f32 "
        "{%0,%1,%2,%3}, {%4,%5,%6,%7}, {%8,%9}, {%0,%1,%2,%3};"
        : "+f"(d[0]), "+f"(d[1]), "+f"(d[2]), "+f"(d[3])
        : "r"(a[0]), "r"(a[1]), "r"(a[2]), "r"(a[3]), "r"(b[0]), "r"(b[1]));
}

__device__ __forceinline__ void split_bf16(float v, __nv_bfloat16& h, __nv_bfloat16& l) {
    h = __float2bfloat16(v);
    l = __float2bfloat16(v - __bfloat162float(h));
}

// ---------------- prep: zero accumulators + split x + split weights (one launch) ----------------
#define XN4  (T_TOK*DIM/4)          // 524288
#define WPER (NE*DIM*FDIM/4)        // 1048576 float4s per weight tensor
#define PREP_TOT (XN4 + 3*WPER)

__global__ void prep_kernel(const float* __restrict__ x,
                            const float* __restrict__ gw,
                            const float* __restrict__ uw,
                            const float* __restrict__ dw) {
    int i = blockIdx.x * blockDim.x + threadIdx.x;
    if (i < NE + 1) {
        if (i < NE) { g_cnt[i] = 0; g_sumP[i] = 0.f; }
        else        g_zsum = 0.f;
    }
    if (i >= PREP_TOT) return;

    const float* src;
    __nv_bfloat16 *oh, *ol;
    size_t j;
    if (i < XN4) { src = x; oh = g_xh; ol = g_xl; j = i; }
    else {
        int k = i - XN4;
        int which = k / WPER;
        j = k - which * WPER;
        src = (which == 0) ? gw : (which == 1) ? uw : dw;
        oh  = (which == 0) ? g_gh : (which == 1) ? g_uh : g_dh;
        ol  = (which == 0) ? g_gl : (which == 1) ? g_ul : g_dl;
    }
    float4 v = ((const float4*)src)[j];
    __nv_bfloat16 h0,h1,h2,h3,l0,l1,l2,l3;
    split_bf16(v.x,h0,l0); split_bf16(v.y,h1,l1);
    split_bf16(v.z,h2,l2); split_bf16(v.w,h3,l3);
    ((__nv_bfloat162*)oh)[2*j]   = __nv_bfloat162(h0,h1);
    ((__nv_bfloat162*)oh)[2*j+1] = __nv_bfloat162(h2,h3);
    ((__nv_bfloat162*)ol)[2*j]   = __nv_bfloat162(l0,l1);
    ((__nv_bfloat162*)ol)[2*j+1] = __nv_bfloat162(l2,l3);
}

// ---------------- router: warp-per-token (coalesced), block-aggregated atomics ----------------
// 1024 threads = 32 warps = 32 tokens per block; 128 blocks. (R9 version — measured 17.3us)
#define RT_TOK 32
__global__ void __launch_bounds__(1024) router_kernel(const float* __restrict__ x,
                                                      const float* __restrict__ rw) {
    __shared__ float s_sumP[NE];
    __shared__ float s_zsum;
    __shared__ int   s_cnt[NE];
    __shared__ int   s_base[NE];
    __shared__ int   s_ebuf[NE][2*RT_TOK];
    __shared__ float s_wbuf[NE][2*RT_TOK];

    int tid  = threadIdx.x;
    int wrp  = tid >> 5;
    int lane = tid & 31;
    int tok  = blockIdx.x * RT_TOK + wrp;

    if (tid < NE) { s_sumP[tid] = 0.f; s_cnt[tid] = 0; }
    if (tid == NE) s_zsum = 0.f;
    __syncthreads();

    const float4* xp = (const float4*)(x + (size_t)tok * DIM);
    float4 xv[4];
#pragma unroll
    for (int i = 0; i < 4; i++) xv[i] = xp[lane * 4 + i];

    float logit[NE];
#pragma unroll
    for (int e = 0; e < NE; e++) {
        const float4* wp = (const float4*)(rw + (size_t)e * DIM);
        float acc = 0.f;
#pragma unroll
        for (int i = 0; i < 4; i++) {
            float4 w4 = wp[lane * 4 + i];
            acc += xv[i].x * w4.x + xv[i].y * w4.y + xv[i].z * w4.z + xv[i].w * w4.w;
        }
#pragma unroll
        for (int o = 16; o > 0; o >>= 1) acc += __shfl_xor_sync(0xffffffffu, acc, o);
        logit[e] = acc;
    }

    if (lane == 0) {
        float m = logit[0];
#pragma unroll
        for (int e = 1; e < NE; e++) m = fmaxf(m, logit[e]);
        float p[NE]; float se = 0.f;
#pragma unroll
        for (int e = 0; e < NE; e++) { p[e] = expf(logit[e] - m); se += p[e]; }
        float inv = 1.f / se;

        int i0 = 0; float v0 = -1.f;
#pragma unroll
        for (int e = 0; e < NE; e++) if (p[e] > v0) { v0 = p[e]; i0 = e; }
        int i1 = -1; float v1 = -1.f;
#pragma unroll
        for (int e = 0; e < NE; e++) if (e != i0 && p[e] > v1) { v1 = p[e]; i1 = e; }

        float s2 = v0 + v1;
        float w0 = v0 / s2, w1 = v1 / s2;

        int p0 = atomicAdd(&s_cnt[i0], 1);
        s_ebuf[i0][p0] = (tok << 1);
        s_wbuf[i0][p0] = w0;
        int p1 = atomicAdd(&s_cnt[i1], 1);
        s_ebuf[i1][p1] = (tok << 1) | 1;
        s_wbuf[i1][p1] = w1;

#pragma unroll
        for (int e = 0; e < NE; e++) atomicAdd(&s_sumP[e], p[e] * inv);
        float lse = m + logf(se);
        atomicAdd(&s_zsum, lse * lse);
    }
    __syncthreads();

    if (tid < NE) {
        s_base[tid] = atomicAdd(&g_cnt[tid], s_cnt[tid]);
        atomicAdd(&g_sumP[tid], s_sumP[tid]);
    }
    if (tid == NE) atomicAdd(&g_zsum, s_zsum);
    __syncthreads();

    if (wrp < NE * 4) {
        int e = wrp >> 2, q = wrp & 3;
        int c = s_cnt[e], b = s_base[e];
        for (int i = q * 32 + lane; i < c; i += 128) {
            g_list[e * T_TOK + b + i] = s_ebuf[e][i];
            g_wgt [e * T_TOK + b + i] = s_wbuf[e][i];
        }
    }
}

// ================= Phase A: gate/up warp-MMA GEMM =================
// Block tile M=64 x N=64, K chunks of 64 (8 chunks), 2-stage pipeline, 2 blocks/SM.
#define GU_STG  55296
#define GU_SMEM (1024 + 2*GU_STG)

__global__ void __launch_bounds__(256, 2) gateup_mma_kernel() {
    extern __shared__ char smem[];
    uint32_t sb = smem_u32(smem);
    int e = blockIdx.z;
    int cnt = g_cnt[e];
    int row0 = blockIdx.y * 64;
    if (row0 >= cnt) return;
    int col0 = blockIdx.x * 64;
    int tid = threadIdx.x, wid = tid >> 5, lid = tid & 31;
    int wm = wid >> 2, wn = wid & 3;          // 2 x 4 warp grid: M32 x N16
    int g = lid >> 2, t2 = (lid & 3) * 2;
    int* sTok = (int*)smem;

    for (int i = tid; i < 64; i += 256) {
        int r = row0 + i;
        sTok[i] = (r < cnt) ? g_list[e * T_TOK + r] : -1;
    }
    __syncthreads();

    const __nv_bfloat16* b0 = g_gh + (size_t)e * DIM * FDIM;   // [D][F]
    const __nv_bfloat16* b1 = g_gl + (size_t)e * DIM * FDIM;
    const __nv_bfloat16* b2 = g_uh + (size_t)e * DIM * FDIM;
    const __nv_bfloat16* b3 = g_ul + (size_t)e * DIM * FDIM;

    float accg[2][2][4] = {}, accu[2][2][4] = {};

    auto stage = [&](int chunk) {
        int kt = chunk * 64;
        uint32_t bb = sb + 1024 + (uint32_t)(chunk & 1) * GU_STG;
#pragma unroll
        for (int it = 0; it < 4; it++) {
            int t = tid + it * 256;
            int arr = t >> 9, u = t & 511, row = u >> 3, seg = u & 7;
            int entry = sTok[row];
            uint32_t bytes = (entry >= 0) ? 16u : 0u;
            const __nv_bfloat16* src = (arr ? g_xl : g_xh)
                + (size_t)((entry >= 0) ? (entry >> 1) : 0) * DIM + kt + seg * 8;
            cp16(bb + arr * 9216 + row * 144 + seg * 16, src, bytes);
        }
#pragma unroll
        for (int it = 0; it < 8; it++) {
            int t = tid + it * 256;
            int arr = t >> 9, u = t & 511, row = u >> 3, seg = u & 7;
            const __nv_bfloat16* src = (arr == 0) ? b0 : (arr == 1) ? b1 : (arr == 2) ? b2 : b3;
            cp16(bb + 18432 + arr * 9216 + row * 144 + seg * 16,
                 src + (size_t)(kt + row) * FDIM + col0 + seg * 8, 16u);
        }
    };

    uint32_t laneO = (uint32_t)(((lid & 7) + ((lid >> 3) & 1) * 8) * 144 + ((lid >> 4) & 1) * 16);

    stage(0); CP_COMMIT();
    for (int c = 0; c < 8; c++) {
        if (c + 1 < 8) { stage(c + 1); CP_COMMIT(); CP_WAITG(1); }
        else           { CP_WAITG(0); }
        __syncthreads();
        uint32_t bb = sb + 1024 + (uint32_t)(c & 1) * GU_STG;
        uint32_t aBase = bb + (uint32_t)(wm * 32) * 144 + laneO;
        uint32_t bBase = bb + 18432 + laneO + (uint32_t)(wn * 16) * 2;
#pragma unroll
        for (int kk = 0; kk < 4; kk++) {
            uint32_t ah[2][4], al[2][4];
#pragma unroll
            for (int mt = 0; mt < 2; mt++) {
                uint32_t aa = aBase + mt * (16 * 144) + kk * 32;
                ldsm_x4(ah[mt], aa);
                ldsm_x4(al[mt], aa + 9216);
            }
            uint32_t ba = bBase + kk * (16 * 144);
            uint32_t bgh[4], bgl[4], buh[4], bul[4];
            ldsm_x4_t(bgh, ba);
            ldsm_x4_t(bgl, ba + 9216);
            ldsm_x4_t(buh, ba + 18432);
            ldsm_x4_t(bul, ba + 27648);
#pragma unroll
            for (int h = 0; h < 2; h++) {
#pragma unroll
                for (int mt = 0; mt < 2; mt++) {
                    mma_bf16(accg[mt][h], ah[mt], bgh + h * 2);
                    mma_bf16(accg[mt][h], ah[mt], bgl + h * 2);
                    mma_bf16(accg[mt][h], al[mt], bgh + h * 2);
                    mma_bf16(accu[mt][h], ah[mt], buh + h * 2);
                    mma_bf16(accu[mt][h], ah[mt], bul + h * 2);
                    mma_bf16(accu[mt][h], al[mt], buh + h * 2);
                }
            }
        }
        __syncthreads();
    }

#pragma unroll
    for (int mt = 0; mt < 2; mt++) {
        int r0 = wm * 32 + mt * 16 + g;
        int e0 = sTok[r0], e1 = sTok[r0 + 8];
#pragma unroll
        for (int h = 0; h < 2; h++) {
            int colg = col0 + wn * 16 + h * 8 + t2;
            const float* dg = accg[mt][h];
            const float* du = accu[mt][h];
            if (e0 >= 0) {
                float h0 = du[0] * (dg[0] / (1.f + expf(-dg[0])));
                float h1 = du[1] * (dg[1] / (1.f + expf(-dg[1])));
                __nv_bfloat16 h0h, h0l, h1h, h1l;
                split_bf16(h0, h0h, h0l); split_bf16(h1, h1h, h1l);
                *(__nv_bfloat162*)(g_hh + (size_t)e0 * FDIM + colg) = __nv_bfloat162(h0h, h1h);
                *(__nv_bfloat162*)(g_hl + (size_t)e0 * FDIM + colg) = __nv_bfloat162(h0l, h1l);
            }
            if (e1 >= 0) {
                float h0 = du[2] * (dg[2] / (1.f + expf(-dg[2])));
                float h1 = du[3] * (dg[3] / (1.f + expf(-dg[3])));
                __nv_bfloat16 h0h, h0l, h1h, h1l;
                split_bf16(h0, h0h, h0l); split_bf16(h1, h1h, h1l);
                *(__nv_bfloat162*)(g_hh + (size_t)e1 * FDIM + colg) = __nv_bfloat162(h0h, h1h);
                *(__nv_bfloat162*)(g_hl + (size_t)e1 * FDIM + colg) = __nv_bfloat162(h0l, h1l);
            }
        }
    }
}

// ================= Phase B: down warp-MMA GEMM =================
// Block tile M=64 x N=64, K=1024 in 16 chunks of 64, 2-stage pipeline, target 3 blocks/SM.
#define DN_STG  36864
#define DN_SMEM (1024 + 2*DN_STG)

__global__ void __launch_bounds__(256, 3) down_mma_kernel() {
    extern __shared__ char smem[];
    uint32_t sb = smem_u32(smem);
    int e = blockIdx.z;
    int cnt = g_cnt[e];
    int row0 = blockIdx.y * 64;
    if (row0 >= cnt) return;
    int col0 = blockIdx.x * 64;
    int tid = threadIdx.x, wid = tid >> 5, lid = tid & 31;
    int wm = wid >> 2, wn = wid & 3;
    int g = lid >> 2, t2 = (lid & 3) * 2;
    int*   sTok = (int*)smem;
    float* sW   = (float*)(smem + 256);

    for (int i = tid; i < 64; i += 256) {
        int r = row0 + i;
        sTok[i] = (r < cnt) ? g_list[e * T_TOK + r] : -1;
        sW[i]   = (r < cnt) ? g_wgt [e * T_TOK + r] : 0.f;
    }
    __syncthreads();

    const __nv_bfloat16* dh = g_dh + (size_t)e * FDIM * DIM;   // [F][D]
    const __nv_bfloat16* dl = g_dl + (size_t)e * FDIM * DIM;

    float acc[2][2][4] = {};

    auto stage = [&](int chunk) {
        int kt = chunk * 64;
        uint32_t bb = sb + 1024 + (uint32_t)(chunk & 1) * DN_STG;
#pragma unroll
        for (int it = 0; it < 4; it++) {
            int t = tid + it * 256;
            int arr = t >> 9, u = t & 511, row = u >> 3, seg = u & 7;
            int entry = sTok[row];
            uint32_t bytes = (entry >= 0) ? 16u : 0u;
            const __nv_bfloat16* src = (arr ? g_hl : g_hh)
                + (size_t)((entry >= 0) ? entry : 0) * FDIM + kt + seg * 8;
            cp16(bb + arr * 9216 + row * 144 + seg * 16, src, bytes);
        }
#pragma unroll
        for (int it = 0; it < 4; it++) {
            int t = tid + it * 256;
            int arr = t >> 9, u = t & 511, row = u >> 3, seg = u & 7;
            const __nv_bfloat16* src = (arr ? dl : dh)
                + (size_t)(kt + row) * DIM + col0 + seg * 8;
            cp16(bb + 18432 + arr * 9216 + row * 144 + seg * 16, src, 16u);
        }
    };

    uint32_t laneO = (uint32_t)(((lid & 7) + ((lid >> 3) & 1) * 8) * 144 + ((lid >> 4) & 1) * 16);

    stage(0); CP_COMMIT();
    for (int c = 0; c < 16; c++) {
        if (c + 1 < 16) { stage(c + 1); CP_COMMIT(); CP_WAITG(1); }
        else            { CP_WAITG(0); }
        __syncthreads();
        uint32_t bb = sb + 1024 + (uint32_t)(c & 1) * DN_STG;
        uint32_t aBase = bb + (uint32_t)(wm * 32) * 144 + laneO;
        uint32_t bBase = bb + 18432 + laneO + (uint32_t)(wn * 16) * 2;
#pragma unroll
        for (int kk = 0; kk < 4; kk++) {
            uint32_t ah[2][4], al[2][4];
#pragma unroll
            for (int mt = 0; mt < 2; mt++) {
                uint32_t aa = aBase + mt * (16 * 144) + kk * 32;
                ldsm_x4(ah[mt], aa);
                ldsm_x4(al[mt], aa + 9216);
            }
            uint32_t ba = bBase + kk * (16 * 144);
            uint32_t bh[4], bl[4];
            ldsm_x4_t(bh, ba);
            ldsm_x4_t(bl, ba + 9216);
#pragma unroll
            for (int h = 0; h < 2; h++) {
#pragma unroll
                for (int mt = 0; mt < 2; mt++) {
                    mma_bf16(acc[mt][h], ah[mt], bh + h * 2);
                    mma_bf16(acc[mt][h], ah[mt], bl + h * 2);
                    mma_bf16(acc[mt][h], al[mt], bh + h * 2);
                }
            }
        }
        __syncthreads();
    }

#pragma unroll
    for (int mt = 0; mt < 2; mt++) {
        int r0 = wm * 32 + mt * 16 + g;
        int e0 = sTok[r0], e1 = sTok[r0 + 8];
        float w0 = sW[r0], w1 = sW[r0 + 8];
#pragma unroll
        for (int h = 0; h < 2; h++) {
            int cg = col0 + wn * 16 + h * 8 + t2;
            const float* d = acc[mt][h];
            if (e0 >= 0) {
                float2 o = make_float2(w0 * d[0], w0 * d[1]);
                *(float2*)(g_pout + (size_t)e0 * DIM + cg) = o;
            }
            if (e1 >= 0) {
                float2 o = make_float2(w1 * d[2], w1 * d[3]);
                *(float2*)(g_pout + (size_t)e1 * DIM + cg) = o;
            }
        }
    }
}

// ---------------- combine pair slots + aux loss (fused) ----------------
__global__ void combine_kernel(float* __restrict__ out, int out_size) {
    int i = blockIdx.x * blockDim.x + threadIdx.x;
    if (blockIdx.x == 0 && threadIdx.x == 0) {
        float lb = 0.f;
#pragma unroll
        for (int e = 0; e < NE; e++)
            lb += ((float)g_cnt[e] / (float)NPAIR) * (g_sumP[e] / (float)T_TOK);
        out[out_size - 1] = 0.01f * (float)NE * lb + 0.001f * (g_zsum / (float)T_TOK);
    }
    const int N4 = T_TOK * DIM / 4;
    const int D4 = DIM / 4;
    if (i >= N4) return;
    int t = i / D4, c = i % D4;
    const float4* p = (const float4*)g_pout;
    float4 a = p[(size_t)(2 * t) * D4 + c];
    float4 b = p[(size_t)(2 * t + 1) * D4 + c];
    ((float4*)out)[i] = make_float4(a.x + b.x, a.y + b.y, a.z + b.z, a.w + b.w);
}

// ---------------- launch ----------------
extern "C" void kernel_launch(void* const* d_in, const int* in_sizes, int n_in,
                              void* d_out, int out_size) {
    const float* x  = (const float*)d_in[0];
    const float* rw = (const float*)d_in[1];
    const float* gw = (const float*)d_in[2];
    const float* uw = (const float*)d_in[3];
    const float* dw = (const float*)d_in[4];
    float* out = (float*)d_out;

    cudaFuncSetAttribute(gateup_mma_kernel, cudaFuncAttributeMaxDynamicSharedMemorySize, GU_SMEM);
    cudaFuncSetAttribute(down_mma_kernel,   cudaFuncAttributeMaxDynamicSharedMemorySize, DN_SMEM);

    prep_kernel<<<(PREP_TOT + 255) / 256, 256>>>(x, gw, uw, dw);
    router_kernel<<<T_TOK / RT_TOK, 1024>>>(x, rw);
    gateup_mma_kernel<<<dim3(FDIM / 64, T_TOK / 64, NE), 256, GU_SMEM>>>();
    down_mma_kernel<<<dim3(DIM / 64, T_TOK / 64, NE), 256, DN_SMEM>>>();
    combine_kernel<<<(T_TOK * DIM / 4 + 255) / 256, 256>>>(out, out_size);
}